// round 10
// baseline (speedup 1.0000x reference)
#include <cuda_runtime.h>
#include <cuda_bf16.h>
#include <cstdint>

// ---------------- problem constants ----------------
#define TT   4
#define BB   16
#define CC   512
#define NN   256
#define HID  2048
#define TBCN (TT*BB*CC*NN)     // 8,388,608
#define NPERS 296              // persistent CTAs = 2 per SM x 148

// ---------------- static scratch ----------------
__device__ float         g_xt  [64L*256*512];    // x transposed, channels-last fp32
__device__ __nv_bfloat16 g_sx  [64L*256*512];    // spikes (x / mlp), bf16
__device__ float         g_q   [64L*256*1536];   // qkv gemm out fp32 (channels-last)
__device__ __nv_bfloat16 g_qs  [64L*256*1536];   // qkv spikes bf16 (att in place in q cols)
__device__ float         g_xat [64L*256*512];    // attention block output fp32
__device__ float         g_h1  [64L*256*2048];   // fc1 out fp32
__device__ __nv_bfloat16 g_h1s [64L*256*2048];   // fc1 spikes bf16
__device__ __nv_bfloat16 g_kvs [64*512];         // kv spikes bf16
__device__ int           g_kvcnt[64*512];        // kv AND-counts (int, exact)
__device__ __nv_bfloat16 g_whi [3145728];        // weights hi bf16: qkv|proj|fc1|fc2
__device__ __nv_bfloat16 g_wlo [3145728];        // weights lo bf16
__device__ float         g_A   [4608];           // folded BN scale
__device__ float         g_Bc  [4608];           // folded BN bias

#define W_QKV  0L
#define W_PROJ 786432L
#define W_FC1  1048576L
#define W_FC2  2097152L

#define BF1 ((unsigned short)0x3F80)

// ---------------- PTX helpers (baseline ISA only) ----------------
__device__ __forceinline__ uint32_t smem_u32(const void* p) {
    uint32_t a;
    asm("{ .reg .u64 t; cvta.to.shared.u64 t, %1; cvt.u32.u64 %0, t; }" : "=r"(a) : "l"(p));
    return a;
}
__device__ __forceinline__ void cp16(uint32_t dst, const void* src) {
    asm volatile("cp.async.cg.shared.global [%0], [%1], 16;" :: "r"(dst), "l"(src));
}
#define CP_COMMIT() asm volatile("cp.async.commit_group;" ::: "memory")
#define CP_WAIT0()  asm volatile("cp.async.wait_group 0;" ::: "memory")

__device__ __forceinline__ void ldm4(uint32_t& r0, uint32_t& r1, uint32_t& r2, uint32_t& r3,
                                     uint32_t addr) {
    asm volatile("ldmatrix.sync.aligned.m8n8.x4.shared.b16 {%0,%1,%2,%3}, [%4];"
                 : "=r"(r0), "=r"(r1), "=r"(r2), "=r"(r3) : "r"(addr));
}
__device__ __forceinline__ void mma16816(float* c, const uint32_t* a, uint32_t b0, uint32_t b1) {
    asm volatile("mma.sync.aligned.m16n8k16.row.col.f32.bf16.bf16.f32 "
                 "{%0,%1,%2,%3}, {%4,%5,%6,%7}, {%8,%9}, {%0,%1,%2,%3};"
                 : "+f"(c[0]), "+f"(c[1]), "+f"(c[2]), "+f"(c[3])
                 : "r"(a[0]), "r"(a[1]), "r"(a[2]), "r"(a[3]), "r"(b0), "r"(b1));
}

// SMEM: per stage A(128x144B) | Bhi(128x144B) | Blo(128x144B); 2 stages; K-chunk 64
#define RS    144
#define STG_A (128*RS)        // 18432
#define STAGE (3*STG_A)       // 55296
#define SMEM_TOT (2*STAGE)    // 110592  (x2 CTAs/SM = 221184 <= 228KB)

// ---------------- merged prep kernel ----------------
// blocks [0,18): BN fold; [18,12306): weight split; [12306,12434): zero kvcnt
__global__ void prep_kernel(const float* __restrict__ qbn, const float* __restrict__ kbn,
                            const float* __restrict__ vbn, const float* __restrict__ pbn,
                            const float* __restrict__ f1bn, const float* __restrict__ f2bn,
                            const float* __restrict__ pb, const float* __restrict__ f1b,
                            const float* __restrict__ f2b,
                            const float* __restrict__ qw, const float* __restrict__ kw,
                            const float* __restrict__ vw, const float* __restrict__ pj,
                            const float* __restrict__ f1, const float* __restrict__ f2)
{
    int blk = blockIdx.x;
    if (blk < 18) {
        int i = blk * 256 + threadIdx.x;
        if (i >= 4608) return;
        const float* bn; int c; int nc; float bias = 0.f;
        if (i < 1536)      { int s = i >> 9; c = i & 511; nc = CC;
                             bn = (s == 0) ? qbn : (s == 1) ? kbn : vbn; }
        else if (i < 2048) { c = i - 1536; nc = CC;  bn = pbn;  bias = pb[c]; }
        else if (i < 4096) { c = i - 2048; nc = HID; bn = f1bn; bias = f1b[c]; }
        else               { c = i - 4096; nc = CC;  bn = f2bn; bias = f2b[c]; }
        float g  = bn[c];
        float be = bn[nc + c];
        float m  = bn[2*nc + c];
        float v  = bn[3*nc + c];
        float a  = g / sqrtf(v + 1e-5f);
        g_A[i]  = a;
        g_Bc[i] = be + (bias - m) * a;
    } else if (blk < 12306) {
        long i = (long)(blk - 18) * 256 + threadIdx.x;
        if (i >= 3145728L) return;
        float w;
        if (i < 786432L)       { long s = i / 262144L, r = i % 262144L;
                                 w = (s == 0) ? qw[r] : (s == 1) ? kw[r] : vw[r]; }
        else if (i < 1048576L) w = pj[i - 786432L];
        else if (i < 2097152L) w = f1[i - 1048576L];
        else                   w = f2[i - 2097152L];
        __nv_bfloat16 h = __float2bfloat16(w);
        g_whi[i] = h;
        g_wlo[i] = __float2bfloat16(w - __bfloat162float(h));
    } else {
        int i = (blk - 12306) * 256 + threadIdx.x;
        g_kvcnt[i] = 0;
    }
}

// fused transpose + shortcut LIF: x[t,b,c,n] -> g_xt[t,b,n,c] fp32 AND g_sx spikes bf16
__global__ void xpose_lif_kernel(const float* __restrict__ x)
{
    __shared__ float t4[4][32][33];
    int b  = blockIdx.z;
    int n0 = blockIdx.x * 32, c0 = blockIdx.y * 32;
    int tx = threadIdx.x, ty = threadIdx.y;  // (32,8)
#pragma unroll
    for (int t = 0; t < TT; t++)
#pragma unroll
        for (int i = 0; i < 4; i++) {
            int c = c0 + ty + i * 8;
            t4[t][ty + i * 8][tx] = x[(((long)t * BB + b) * CC + c) * NN + n0 + tx];
        }
    __syncthreads();
#pragma unroll
    for (int i = 0; i < 4; i++) {
        int n = n0 + ty + i * 8;
        int c = c0 + tx;
        float v = 0.f;
#pragma unroll
        for (int t = 0; t < TT; t++) {
            float xv = t4[t][tx][ty + i * 8];
            long o = (((long)t * BB + b) * NN + n) * CC + c;
            g_xt[o] = xv;
            v = 0.5f * (v + xv);
            bool sp = (v >= 1.0f);
            g_sx[o] = __float2bfloat16(sp ? 1.f : 0.f);
            if (sp) v = 0.f;
        }
    }
}

// vectorized LIF: 4 elems/thread, fp32 in -> bf16 spikes out
__global__ void lif4_kernel(const float4* __restrict__ in, ushort4* __restrict__ out,
                            int n4, long t4stride, float vth)
{
    int i = blockIdx.x * 256 + threadIdx.x;
    if (i >= n4) return;
    float vx = 0.f, vy = 0.f, vz = 0.f, vw = 0.f;
#pragma unroll
    for (int t = 0; t < TT; t++) {
        float4 xv = in[(long)t * t4stride + i];
        ushort4 s;
        vx = 0.5f * (vx + xv.x); s.x = (vx >= vth) ? BF1 : 0; if (vx >= vth) vx = 0.f;
        vy = 0.5f * (vy + xv.y); s.y = (vy >= vth) ? BF1 : 0; if (vy >= vth) vy = 0.f;
        vz = 0.5f * (vz + xv.z); s.z = (vz >= vth) ? BF1 : 0; if (vz >= vth) vz = 0.f;
        vw = 0.5f * (vw + xv.w); s.w = (vw >= vth) ? BF1 : 0; if (vw >= vth) vw = 0.f;
        out[(long)t * t4stride + i] = s;
    }
}

// coalesced kv AND-count: block = (tb, ngroup of 64 rows); thread owns 2 channels.
__global__ void kvcount_kernel()
{
    int tb = blockIdx.x >> 2;
    int ng = blockIdx.x & 3;
    int t  = threadIdx.x;              // owns channels 2t, 2t+1
    const unsigned int* qs = (const unsigned int*)g_qs;
    long base = (long)tb * 256 * 768;
    int c0 = 0, c1 = 0;
#pragma unroll 8
    for (int n = ng * 64; n < ng * 64 + 64; n++) {
        unsigned int k = qs[base + (long)n * 768 + 256 + t];
        unsigned int v = qs[base + (long)n * 768 + 512 + t];
        unsigned int a = k & v;
        c0 += (a & 0xFFFFu) ? 1 : 0;
        c1 += (a >> 16)     ? 1 : 0;
    }
    atomicAdd(&g_kvcnt[tb * 512 + 2 * t],     c0);
    atomicAdd(&g_kvcnt[tb * 512 + 2 * t + 1], c1);
}

// talking-heads LIF over counts (vth=0.5)
__global__ void kvlif2_kernel()
{
    int idx = blockIdx.x * 256 + threadIdx.x;   // 8192 = 16 b x 512 c
    int b = idx >> 9, c = idx & 511;
    float v = 0.f;
#pragma unroll
    for (int t = 0; t < TT; t++) {
        int tb = t * BB + b;
        float s = (float)g_kvcnt[tb * 512 + c];
        v = 0.5f * (v + s);
        bool sp = (v >= 0.5f);
        g_kvs[tb * 512 + c] = __float2bfloat16(sp ? 1.f : 0.f);
        if (sp) v = 0.f;
    }
}

// blocks [0,8192): att = q&kv (bitwise, 4 lanes); blocks [8192,16384): vh output
__global__ void attvh_kernel(float4* __restrict__ vh)
{
    int bi = blockIdx.x;
    const uint2* qs2 = (const uint2*)g_qs;
    if (bi < 8192) {
        long i = (long)bi * 256 + threadIdx.x;
        int c4 = (int)(i & 127);
        int n  = (int)((i >> 7) & 255);
        int tb = (int)(i >> 15);
        long qq = (((long)tb * 256 + n) * 1536 + c4 * 4) >> 2;
        uint2 q = ((uint2*)g_qs)[qq];
        uint2 kv = ((const uint2*)g_kvs)[((long)tb * 512 + c4 * 4) >> 2];
        q.x &= kv.x; q.y &= kv.y;
        ((uint2*)g_qs)[qq] = q;
    } else {
        long i = (long)(bi - 8192) * 256 + threadIdx.x;
        int ch4 = (int)(i & 15);
        int n   = (int)((i >> 4) & 255);
        int h   = (int)((i >> 12) & 7);
        int tb  = (int)(i >> 15);
        uint2 s = qs2[(((long)tb * 256 + n) * 1536 + 1024 + h * 64 + ch4 * 4) >> 2];
        float4 o;
        o.x = (s.x & 0xFFFFu)  ? 1.f : 0.f;
        o.y = (s.x >> 16)      ? 1.f : 0.f;
        o.z = (s.y & 0xFFFFu)  ? 1.f : 0.f;
        o.w = (s.y >> 16)      ? 1.f : 0.f;
        vh[i] = o;
    }
}

// ---------------- HMMA GEMM (persistent tiles) ----------------
// 256 threads, 8 warps (2x4), warp tile 64x32, 2-stage cp.async (K-chunk 64),
// 1 sync/chunk, 2 CTAs/SM, NPERS persistent CTAs looping over tiles with
// cross-tile chunk prefetch (disabled for cm, which drains before its smem epilogue).
__global__ void __launch_bounds__(256, 2)
mma_gemm(const __nv_bfloat16* __restrict__ A, long a_bs, int lda,
         const __nv_bfloat16* __restrict__ Whi, const __nv_bfloat16* __restrict__ Wlo,
         long wbase, int K,
         const float* __restrict__ Asc, const float* __restrict__ Bsc,
         const float* __restrict__ Res, long res_bs,
         float* __restrict__ Out, long out_bs, int Mout, int cm,
         int gx, int gy, int ntiles)
{
    extern __shared__ char sm[];
    const uint32_t smb = smem_u32(sm);

    const int tid  = threadIdx.x;
    const int lane = tid & 31;
    const int wid  = tid >> 5;          // 8 warps
    const int wm   = wid & 1;           // 2 M-groups of 64 rows
    const int wn   = wid >> 1;          // 4 N-groups of 32 cols
    const int nch  = K >> 6;

    const int arow = (lane & 7) + ((lane >> 3) & 1) * 8;
    const int ac8  = (lane >> 4) * 16;
    const int brow = (lane & 7) + (lane >> 4) * 8;
    const int bc8  = ((lane >> 3) & 1) * 16;

    auto tile_ptrs = [&](int tt, const __nv_bfloat16*& Ab,
                         const __nv_bfloat16*& Hb, const __nv_bfloat16*& Lb) {
        int bx = tt % gx; int rem = tt / gx;
        int by = rem % gy; int bz = rem / gy;
        Ab = A + (long)bz * a_bs + (long)(bx * 128) * lda;
        Hb = Whi + wbase + (long)(by * 128) * K;
        Lb = Wlo + wbase + (long)(by * 128) * K;
    };

    auto load_stage = [&](int s, const __nv_bfloat16* Ab, const __nv_bfloat16* Hb,
                          const __nv_bfloat16* Lb, int kc) {
        uint32_t base = smb + s * STAGE;
#pragma unroll
        for (int jj = 0; jj < 4; jj++) {
            int u = jj * 256 + tid;
            int r = u >> 3, c16 = u & 7;
            cp16(base + r * RS + c16 * 16, Ab + (long)r * lda + kc * 64 + c16 * 8);
        }
#pragma unroll
        for (int jj = 0; jj < 4; jj++) {
            int u = jj * 256 + tid;
            int r = u >> 3, c16 = u & 7;
            cp16(base + STG_A + r * RS + c16 * 16, Hb + (long)r * K + kc * 64 + c16 * 8);
        }
#pragma unroll
        for (int jj = 0; jj < 4; jj++) {
            int u = jj * 256 + tid;
            int r = u >> 3, c16 = u & 7;
            cp16(base + 2 * STG_A + r * RS + c16 * 16, Lb + (long)r * K + kc * 64 + c16 * 8);
        }
    };

    int t = blockIdx.x;
    const __nv_bfloat16 *cA, *cH, *cL;
    tile_ptrs(t, cA, cH, cL);
    load_stage(0, cA, cH, cL, 0);
    CP_COMMIT();
    int cs = 0;

    float acc[4][4][4];

    while (true) {
#pragma unroll
        for (int a_ = 0; a_ < 4; a_++)
#pragma unroll
            for (int b_ = 0; b_ < 4; b_++)
#pragma unroll
                for (int r_ = 0; r_ < 4; r_++) acc[a_][b_][r_] = 0.f;

        int bx = t % gx; int rem = t / gx;
        int by = rem % gy; int bz = rem / gy;
        const int n0 = bx * 128, c0 = by * 128, tb = bz;

        int nt = t + gridDim.x;
        bool have_next = (nt < ntiles);
        const __nv_bfloat16 *nA = nullptr, *nH = nullptr, *nL = nullptr;
        if (have_next) tile_ptrs(nt, nA, nH, nL);

        for (int ch = 0; ch < nch; ch++) {
            CP_WAIT0();
            __syncthreads();
            if (ch + 1 < nch)            { load_stage((cs + 1) & 1, cA, cH, cL, ch + 1); CP_COMMIT(); }
            else if (have_next && !cm)   { load_stage((cs + 1) & 1, nA, nH, nL, 0);      CP_COMMIT(); }

            const uint32_t ab = smb + (cs & 1) * STAGE;
            const uint32_t hb = ab + STG_A;
            const uint32_t lb = hb + STG_A;

#pragma unroll
            for (int kt = 0; kt < 4; kt++) {
                const int ko = kt * 32;
                uint32_t a[4][4];
#pragma unroll
                for (int mt = 0; mt < 4; mt++)
                    ldm4(a[mt][0], a[mt][1], a[mt][2], a[mt][3],
                         ab + (wm * 64 + mt * 16 + arow) * RS + ko + ac8);

                uint32_t bh[8], bl[8];
#pragma unroll
                for (int p = 0; p < 2; p++) {
                    ldm4(bh[p*4+0], bh[p*4+1], bh[p*4+2], bh[p*4+3],
                         hb + (wn * 32 + p * 16 + brow) * RS + ko + bc8);
                    ldm4(bl[p*4+0], bl[p*4+1], bl[p*4+2], bl[p*4+3],
                         lb + (wn * 32 + p * 16 + brow) * RS + ko + bc8);
                }
#pragma unroll
                for (int g = 0; g < 4; g++) {
                    int bi = (g >> 1) * 4 + (g & 1) * 2;
#pragma unroll
                    for (int mt = 0; mt < 4; mt++)
                        mma16816(acc[mt][g], a[mt], bh[bi], bh[bi + 1]);
                }
#pragma unroll
                for (int g = 0; g < 4; g++) {
                    int bi = (g >> 1) * 4 + (g & 1) * 2;
#pragma unroll
                    for (int mt = 0; mt < 4; mt++)
                        mma16816(acc[mt][g], a[mt], bl[bi], bl[bi + 1]);
                }
            }
            cs++;
        }

        // ---------------- per-tile epilogue ----------------
        if (!cm) {
#pragma unroll
            for (int mt = 0; mt < 4; mt++) {
#pragma unroll
                for (int g = 0; g < 4; g++) {
                    int col = c0 + wn * 32 + g * 8 + (lane & 3) * 2;
                    int row = n0 + wm * 64 + mt * 16 + (lane >> 2);
                    float sA0 = Asc[col], sA1 = Asc[col + 1];
                    float sB0 = Bsc[col], sB1 = Bsc[col + 1];
                    float v00 = acc[mt][g][0] * sA0 + sB0;
                    float v01 = acc[mt][g][1] * sA1 + sB1;
                    float v10 = acc[mt][g][2] * sA0 + sB0;
                    float v11 = acc[mt][g][3] * sA1 + sB1;
                    if (Res) {
                        const float* r0 = Res + (long)tb * res_bs + (long)row * Mout + col;
                        float2 ra = *(const float2*)r0;
                        float2 rb = *(const float2*)(r0 + 8 * Mout);
                        v00 += ra.x; v01 += ra.y; v10 += rb.x; v11 += rb.y;
                    }
                    float* o0 = Out + (long)tb * out_bs + (long)row * Mout + col;
                    float2 w0; w0.x = v00; w0.y = v01;
                    float2 w1; w1.x = v10; w1.y = v11;
                    *(float2*)o0 = w0;
                    *(float2*)(o0 + 8 * Mout) = w1;
                }
            }
        } else {
            // drained pipeline (no cross-tile prefetch in cm mode): smem is free
            __syncthreads();
            float* sf = (float*)sm;
#pragma unroll
            for (int mt = 0; mt < 4; mt++) {
#pragma unroll
                for (int g = 0; g < 4; g++) {
                    int cl = wn * 32 + g * 8 + (lane & 3) * 2;
                    int rl = wm * 64 + mt * 16 + (lane >> 2);
                    int col = c0 + cl, row = n0 + rl;
                    float sA0 = Asc[col], sA1 = Asc[col + 1];
                    float sB0 = Bsc[col], sB1 = Bsc[col + 1];
                    float v00 = acc[mt][g][0] * sA0 + sB0;
                    float v01 = acc[mt][g][1] * sA1 + sB1;
                    float v10 = acc[mt][g][2] * sA0 + sB0;
                    float v11 = acc[mt][g][3] * sA1 + sB1;
                    const float* r0 = Res + (long)tb * res_bs + (long)row * Mout + col;
                    float2 ra = *(const float2*)r0;
                    float2 rb = *(const float2*)(r0 + 8 * Mout);
                    v00 += ra.x; v01 += ra.y; v10 += rb.x; v11 += rb.y;
                    sf[cl * 132 + rl]           = v00;
                    sf[(cl + 1) * 132 + rl]     = v01;
                    sf[cl * 132 + rl + 8]       = v10;
                    sf[(cl + 1) * 132 + rl + 8] = v11;
                }
            }
            __syncthreads();
#pragma unroll
            for (int i = 0; i < 16; i++) {
                int c = wid * 16 + i;
                float* orow = Out + (long)tb * out_bs + (long)(c0 + c) * NN + n0;
#pragma unroll
                for (int j = 0; j < 4; j++)
                    orow[lane + j * 32] = sf[c * 132 + lane + j * 32];
            }
            __syncthreads();   // all sf reads done before next tile's loads overwrite
        }

        if (!have_next) break;
        if (cm) { load_stage(cs & 1, nA, nH, nL, 0); CP_COMMIT(); }
        cA = nA; cH = nH; cL = nL;
        t = nt;
    }
}

// ---------------- launch ----------------
extern "C" void kernel_launch(void* const* d_in, const int* in_sizes, int n_in,
                              void* d_out, int out_size)
{
    const float* x      = (const float*)d_in[0];
    const float* q_w    = (const float*)d_in[1];
    const float* k_w    = (const float*)d_in[2];
    const float* v_w    = (const float*)d_in[3];
    const float* proj_w = (const float*)d_in[4];
    const float* proj_b = (const float*)d_in[5];
    const float* fc1_w  = (const float*)d_in[6];
    const float* fc1_b  = (const float*)d_in[7];
    const float* fc2_w  = (const float*)d_in[8];
    const float* fc2_b  = (const float*)d_in[9];
    const float* q_bn   = (const float*)d_in[10];
    const float* k_bn   = (const float*)d_in[11];
    const float* v_bn   = (const float*)d_in[12];
    const float* proj_bn= (const float*)d_in[13];
    const float* fc1_bn = (const float*)d_in[14];
    const float* fc2_bn = (const float*)d_in[15];
    float* out = (float*)d_out;

    cudaFuncSetAttribute(mma_gemm, cudaFuncAttributeMaxDynamicSharedMemorySize, SMEM_TOT);

    float *p_xt, *p_q, *p_xat, *p_h1, *p_A, *p_Bc;
    __nv_bfloat16 *p_sx, *p_qs, *p_h1s, *p_whi, *p_wlo;
    cudaGetSymbolAddress((void**)&p_xt,  g_xt);
    cudaGetSymbolAddress((void**)&p_sx,  g_sx);
    cudaGetSymbolAddress((void**)&p_q,   g_q);
    cudaGetSymbolAddress((void**)&p_qs,  g_qs);
    cudaGetSymbolAddress((void**)&p_xat, g_xat);
    cudaGetSymbolAddress((void**)&p_h1,  g_h1);
    cudaGetSymbolAddress((void**)&p_h1s, g_h1s);
    cudaGetSymbolAddress((void**)&p_whi, g_whi);
    cudaGetSymbolAddress((void**)&p_wlo, g_wlo);
    cudaGetSymbolAddress((void**)&p_A,   g_A);
    cudaGetSymbolAddress((void**)&p_Bc,  g_Bc);

    // merged prep: BN fold + weight split + kvcnt zero
    prep_kernel<<<12434, 256>>>(q_bn, k_bn, v_bn, proj_bn, fc1_bn, fc2_bn,
                                proj_b, fc1_b, fc2_b,
                                q_w, k_w, v_w, proj_w, fc1_w, fc2_w);
    xpose_lif_kernel<<<dim3(8, 16, 16), dim3(32, 8)>>>(x);

    // qkv GEMM (Mout=1536 stacked): tiles = 2 x 12 x 64 = 1536
    mma_gemm<<<NPERS, 256, SMEM_TOT>>>(p_sx, (long)NN*CC, CC,
                                       p_whi, p_wlo, W_QKV, CC,
                                       p_A, p_Bc, nullptr, 0,
                                       p_q, (long)NN*1536, 1536, 0,
                                       2, 12, 1536);
    lif4_kernel<<<6144, 256>>>((const float4*)p_q, (ushort4*)p_qs,
                               BB*NN*1536/4, (long)BB*NN*1536/4, 1.0f);

    kvcount_kernel<<<256, 256>>>();
    kvlif2_kernel<<<32, 256>>>();
    attvh_kernel<<<16384, 256>>>((float4*)(out + (long)TBCN));

    // proj GEMM + BN + identity(x): tiles = 2 x 4 x 64 = 512
    mma_gemm<<<NPERS, 256, SMEM_TOT>>>(p_qs, (long)NN*1536, 1536,
                                       p_whi, p_wlo, W_PROJ, CC,
                                       p_A + 1536, p_Bc + 1536, p_xt, (long)NN*CC,
                                       p_xat, (long)NN*CC, CC, 0,
                                       2, 4, 512);
    lif4_kernel<<<2048, 256>>>((const float4*)p_xat, (ushort4*)p_sx,
                               BB*NN*CC/4, (long)BB*NN*CC/4, 1.0f);

    // fc1 GEMM: tiles = 2 x 16 x 64 = 2048
    mma_gemm<<<NPERS, 256, SMEM_TOT>>>(p_sx, (long)NN*CC, CC,
                                       p_whi, p_wlo, W_FC1, CC,
                                       p_A + 2048, p_Bc + 2048, nullptr, 0,
                                       p_h1, (long)NN*HID, HID, 0,
                                       2, 16, 2048);
    lif4_kernel<<<8192, 256>>>((const float4*)p_h1, (ushort4*)p_h1s,
                               BB*NN*HID/4, (long)BB*NN*HID/4, 1.0f);

    // fc2 GEMM + BN + idm(x_attn) -> d_out (channel-major): tiles = 2 x 4 x 64 = 512
    mma_gemm<<<NPERS, 256, SMEM_TOT>>>(p_h1s, (long)NN*HID, HID,
                                       p_whi, p_wlo, W_FC2, HID,
                                       p_A + 4096, p_Bc + 4096, p_xat, (long)NN*CC,
                                       out, (long)CC*NN, CC, 1,
                                       2, 4, 512);
}

// round 11
// speedup vs baseline: 1.0585x; 1.0585x over previous
#include <cuda_runtime.h>
#include <cuda_bf16.h>
#include <cstdint>

// ---------------- problem constants ----------------
#define TT   4
#define BB   16
#define CC   512
#define NN   256
#define HID  2048
#define TBCN (TT*BB*CC*NN)     // 8,388,608

// ---------------- static scratch ----------------
__device__ float         g_xt  [64L*256*512];    // x transposed, channels-last fp32
__device__ __nv_bfloat16 g_sx  [64L*256*512];    // spikes (x / mlp), bf16
__device__ float         g_q   [64L*256*1536];   // qkv gemm out fp32 (channels-last)
__device__ __nv_bfloat16 g_qs  [64L*256*1536];   // qkv spikes bf16 (att in place in q cols)
__device__ float         g_xat [64L*256*512];    // attention block output fp32
__device__ float         g_h1  [64L*256*2048];   // fc1 out fp32
__device__ __nv_bfloat16 g_h1s [64L*256*2048];   // fc1 spikes bf16
__device__ __nv_bfloat16 g_kvs [64*512];         // kv spikes bf16
__device__ int           g_kvcnt[64*512];        // kv AND-counts (int, exact)
__device__ __nv_bfloat16 g_whi [3145728];        // weights hi bf16: qkv|proj|fc1|fc2
__device__ __nv_bfloat16 g_wlo [3145728];        // weights lo bf16
__device__ float         g_A   [4608];           // folded BN scale
__device__ float         g_Bc  [4608];           // folded BN bias

#define W_QKV  0L
#define W_PROJ 786432L
#define W_FC1  1048576L
#define W_FC2  2097152L

#define BF1 ((unsigned short)0x3F80)

// ---------------- PTX helpers (baseline ISA only) ----------------
__device__ __forceinline__ uint32_t smem_u32(const void* p) {
    uint32_t a;
    asm("{ .reg .u64 t; cvta.to.shared.u64 t, %1; cvt.u32.u64 %0, t; }" : "=r"(a) : "l"(p));
    return a;
}
__device__ __forceinline__ void cp16(uint32_t dst, const void* src) {
    asm volatile("cp.async.cg.shared.global [%0], [%1], 16;" :: "r"(dst), "l"(src));
}
#define CP_COMMIT() asm volatile("cp.async.commit_group;" ::: "memory")
#define CP_WAIT0()  asm volatile("cp.async.wait_group 0;" ::: "memory")

__device__ __forceinline__ void ldm4(uint32_t& r0, uint32_t& r1, uint32_t& r2, uint32_t& r3,
                                     uint32_t addr) {
    asm volatile("ldmatrix.sync.aligned.m8n8.x4.shared.b16 {%0,%1,%2,%3}, [%4];"
                 : "=r"(r0), "=r"(r1), "=r"(r2), "=r"(r3) : "r"(addr));
}
__device__ __forceinline__ void mma16816(float* c, const uint32_t* a, uint32_t b0, uint32_t b1) {
    asm volatile("mma.sync.aligned.m16n8k16.row.col.f32.bf16.bf16.f32 "
                 "{%0,%1,%2,%3}, {%4,%5,%6,%7}, {%8,%9}, {%0,%1,%2,%3};"
                 : "+f"(c[0]), "+f"(c[1]), "+f"(c[2]), "+f"(c[3])
                 : "r"(a[0]), "r"(a[1]), "r"(a[2]), "r"(a[3]), "r"(b0), "r"(b1));
}

// SMEM: per stage A(128x144B) | Bhi(128x144B) | Blo(128x144B); 2 stages; K-chunk 64
#define RS    144
#define STG_A (128*RS)        // 18432
#define STAGE (3*STG_A)       // 55296
#define SMEM_TOT (2*STAGE)    // 110592  (x2 CTAs/SM = 221184 <= 228KB)

// ---------------- merged prep kernel ----------------
// blocks [0,18): BN fold; [18,12306): weight split; [12306,12434): zero kvcnt
__global__ void prep_kernel(const float* __restrict__ qbn, const float* __restrict__ kbn,
                            const float* __restrict__ vbn, const float* __restrict__ pbn,
                            const float* __restrict__ f1bn, const float* __restrict__ f2bn,
                            const float* __restrict__ pb, const float* __restrict__ f1b,
                            const float* __restrict__ f2b,
                            const float* __restrict__ qw, const float* __restrict__ kw,
                            const float* __restrict__ vw, const float* __restrict__ pj,
                            const float* __restrict__ f1, const float* __restrict__ f2)
{
    int blk = blockIdx.x;
    if (blk < 18) {
        int i = blk * 256 + threadIdx.x;
        if (i >= 4608) return;
        const float* bn; int c; int nc; float bias = 0.f;
        if (i < 1536)      { int s = i >> 9; c = i & 511; nc = CC;
                             bn = (s == 0) ? qbn : (s == 1) ? kbn : vbn; }
        else if (i < 2048) { c = i - 1536; nc = CC;  bn = pbn;  bias = pb[c]; }
        else if (i < 4096) { c = i - 2048; nc = HID; bn = f1bn; bias = f1b[c]; }
        else               { c = i - 4096; nc = CC;  bn = f2bn; bias = f2b[c]; }
        float g  = bn[c];
        float be = bn[nc + c];
        float m  = bn[2*nc + c];
        float v  = bn[3*nc + c];
        float a  = g / sqrtf(v + 1e-5f);
        g_A[i]  = a;
        g_Bc[i] = be + (bias - m) * a;
    } else if (blk < 12306) {
        long i = (long)(blk - 18) * 256 + threadIdx.x;
        if (i >= 3145728L) return;
        float w;
        if (i < 786432L)       { long s = i / 262144L, r = i % 262144L;
                                 w = (s == 0) ? qw[r] : (s == 1) ? kw[r] : vw[r]; }
        else if (i < 1048576L) w = pj[i - 786432L];
        else if (i < 2097152L) w = f1[i - 1048576L];
        else                   w = f2[i - 2097152L];
        __nv_bfloat16 h = __float2bfloat16(w);
        g_whi[i] = h;
        g_wlo[i] = __float2bfloat16(w - __bfloat162float(h));
    } else {
        int i = (blk - 12306) * 256 + threadIdx.x;
        g_kvcnt[i] = 0;
    }
}

// fused transpose + shortcut LIF: x[t,b,c,n] -> g_xt[t,b,n,c] fp32 AND g_sx spikes bf16
__global__ void xpose_lif_kernel(const float* __restrict__ x)
{
    __shared__ float t4[4][32][33];
    int b  = blockIdx.z;
    int n0 = blockIdx.x * 32, c0 = blockIdx.y * 32;
    int tx = threadIdx.x, ty = threadIdx.y;  // (32,8)
#pragma unroll
    for (int t = 0; t < TT; t++)
#pragma unroll
        for (int i = 0; i < 4; i++) {
            int c = c0 + ty + i * 8;
            t4[t][ty + i * 8][tx] = x[(((long)t * BB + b) * CC + c) * NN + n0 + tx];
        }
    __syncthreads();
#pragma unroll
    for (int i = 0; i < 4; i++) {
        int n = n0 + ty + i * 8;
        int c = c0 + tx;
        float v = 0.f;
#pragma unroll
        for (int t = 0; t < TT; t++) {
            float xv = t4[t][tx][ty + i * 8];
            long o = (((long)t * BB + b) * NN + n) * CC + c;
            g_xt[o] = xv;
            v = 0.5f * (v + xv);
            bool sp = (v >= 1.0f);
            g_sx[o] = __float2bfloat16(sp ? 1.f : 0.f);
            if (sp) v = 0.f;
        }
    }
}

// vectorized LIF: 4 elems/thread, fp32 in -> bf16 spikes out.
// If vhout != nullptr (qkv path), threads covering the v-channel region
// [1024,1536) also write the fp32 vh tensor directly (spike bits copied).
__global__ void lif4_kernel(const float4* __restrict__ in, ushort4* __restrict__ out,
                            int n4, long t4stride, float vth, float4* __restrict__ vhout)
{
    int i = blockIdx.x * 256 + threadIdx.x;
    if (i >= n4) return;

    // qkv decode (valid only when vhout != nullptr): i -> (b, n, c4)
    int c4 = i % 384;                  // 1536/4 quads per (b,n)
    int n  = (i / 384) & 255;
    int b  = i / 98304;                // 384*256
    bool do_vh = (vhout != nullptr) && (c4 >= 256);
    int ch4 = c4 - 256;                // quad index within v region
    int h   = ch4 >> 4;                // 64 ch per head = 16 quads
    int vbase = 0;
    if (do_vh) vbase = n * 16 + (ch4 & 15);

    float vx = 0.f, vy = 0.f, vz = 0.f, vw = 0.f;
#pragma unroll
    for (int t = 0; t < TT; t++) {
        float4 xv = in[(long)t * t4stride + i];
        ushort4 s;
        vx = 0.5f * (vx + xv.x); s.x = (vx >= vth) ? BF1 : 0; if (vx >= vth) vx = 0.f;
        vy = 0.5f * (vy + xv.y); s.y = (vy >= vth) ? BF1 : 0; if (vy >= vth) vy = 0.f;
        vz = 0.5f * (vz + xv.z); s.z = (vz >= vth) ? BF1 : 0; if (vz >= vth) vz = 0.f;
        vw = 0.5f * (vw + xv.w); s.w = (vw >= vth) ? BF1 : 0; if (vw >= vth) vw = 0.f;
        out[(long)t * t4stride + i] = s;
        if (do_vh) {
            float4 o;
            o.x = s.x ? 1.f : 0.f;
            o.y = s.y ? 1.f : 0.f;
            o.z = s.z ? 1.f : 0.f;
            o.w = s.w ? 1.f : 0.f;
            vhout[((long)((t * BB + b) * 8 + h)) * 4096 + vbase] = o;
        }
    }
}

// coalesced kv AND-count: block = (tb, ngroup of 64 rows); thread owns 2 channels.
__global__ void kvcount_kernel()
{
    int tb = blockIdx.x >> 2;
    int ng = blockIdx.x & 3;
    int t  = threadIdx.x;              // owns channels 2t, 2t+1
    const unsigned int* qs = (const unsigned int*)g_qs;
    long base = (long)tb * 256 * 768;
    int c0 = 0, c1 = 0;
#pragma unroll 8
    for (int n = ng * 64; n < ng * 64 + 64; n++) {
        unsigned int k = qs[base + (long)n * 768 + 256 + t];
        unsigned int v = qs[base + (long)n * 768 + 512 + t];
        unsigned int a = k & v;
        c0 += (a & 0xFFFFu) ? 1 : 0;
        c1 += (a >> 16)     ? 1 : 0;
    }
    atomicAdd(&g_kvcnt[tb * 512 + 2 * t],     c0);
    atomicAdd(&g_kvcnt[tb * 512 + 2 * t + 1], c1);
}

// talking-heads LIF over counts (vth=0.5)
__global__ void kvlif2_kernel()
{
    int idx = blockIdx.x * 256 + threadIdx.x;   // 8192 = 16 b x 512 c
    int b = idx >> 9, c = idx & 511;
    float v = 0.f;
#pragma unroll
    for (int t = 0; t < TT; t++) {
        int tb = t * BB + b;
        float s = (float)g_kvcnt[tb * 512 + c];
        v = 0.5f * (v + s);
        bool sp = (v >= 0.5f);
        g_kvs[tb * 512 + c] = __float2bfloat16(sp ? 1.f : 0.f);
        if (sp) v = 0.f;
    }
}

// att = q & kv (bitwise over bf16 spike lanes), in place on q region of g_qs
__global__ void att_kernel()
{
    long i = (long)blockIdx.x * 256 + threadIdx.x;      // quads over 64*256*512
    int c4 = (int)(i & 127);
    int n  = (int)((i >> 7) & 255);
    int tb = (int)(i >> 15);
    long qq = (((long)tb * 256 + n) * 1536 + c4 * 4) >> 2;   // uint2 index (4 bf16)
    uint2 q = ((uint2*)g_qs)[qq];
    uint2 kv = ((const uint2*)g_kvs)[((long)tb * 512 + c4 * 4) >> 2];
    q.x &= kv.x; q.y &= kv.y;
    ((uint2*)g_qs)[qq] = q;
}

// ---------------- HMMA GEMM ----------------
// 256 threads, 8 warps (2x4), warp tile 64x32, 2-stage cp.async (K-chunk 64),
// 1 sync/chunk, 2 CTAs/SM.  (best measured config: 140us on qkv)
__global__ void __launch_bounds__(256, 2)
mma_gemm(const __nv_bfloat16* __restrict__ A, long a_bs, int lda,
         const __nv_bfloat16* __restrict__ Whi, const __nv_bfloat16* __restrict__ Wlo,
         long wbase, int K,
         const float* __restrict__ Asc, const float* __restrict__ Bsc,
         const float* __restrict__ Res, long res_bs,
         float* __restrict__ Out, long out_bs, int Mout, int cm)
{
    extern __shared__ char sm[];
    const uint32_t smb = smem_u32(sm);

    const int tid  = threadIdx.x;
    const int lane = tid & 31;
    const int wid  = tid >> 5;          // 8 warps
    const int wm   = wid & 1;           // 2 M-groups of 64 rows
    const int wn   = wid >> 1;          // 4 N-groups of 32 cols
    const int n0   = blockIdx.x * 128;  // spatial
    const int c0   = blockIdx.y * 128;  // channels
    const int tb   = blockIdx.z;
    const int nch  = K >> 6;

    const __nv_bfloat16* Ab = A + (long)tb * a_bs + (long)n0 * lda;
    const __nv_bfloat16* Hb = Whi + wbase + (long)c0 * K;
    const __nv_bfloat16* Lb = Wlo + wbase + (long)c0 * K;

    const int arow = (lane & 7) + ((lane >> 3) & 1) * 8;
    const int ac8  = (lane >> 4) * 16;
    const int brow = (lane & 7) + (lane >> 4) * 8;
    const int bc8  = ((lane >> 3) & 1) * 16;

    float acc[4][4][4];
#pragma unroll
    for (int a_ = 0; a_ < 4; a_++)
#pragma unroll
        for (int b_ = 0; b_ < 4; b_++)
#pragma unroll
            for (int r_ = 0; r_ < 4; r_++) acc[a_][b_][r_] = 0.f;

    auto load_stage = [&](int s, int kc) {
        uint32_t base = smb + s * STAGE;
#pragma unroll
        for (int jj = 0; jj < 4; jj++) {
            int u = jj * 256 + tid;            // 0..1023
            int r = u >> 3, c16 = u & 7;
            cp16(base + r * RS + c16 * 16, Ab + (long)r * lda + kc * 64 + c16 * 8);
        }
#pragma unroll
        for (int jj = 0; jj < 4; jj++) {
            int u = jj * 256 + tid;
            int r = u >> 3, c16 = u & 7;
            cp16(base + STG_A + r * RS + c16 * 16, Hb + (long)r * K + kc * 64 + c16 * 8);
        }
#pragma unroll
        for (int jj = 0; jj < 4; jj++) {
            int u = jj * 256 + tid;
            int r = u >> 3, c16 = u & 7;
            cp16(base + 2 * STG_A + r * RS + c16 * 16, Lb + (long)r * K + kc * 64 + c16 * 8);
        }
    };

    load_stage(0, 0);
    CP_COMMIT();

    for (int ch = 0; ch < nch; ch++) {
        CP_WAIT0();            // this thread's loads for chunk ch complete
        __syncthreads();       // all threads' loads done AND iter ch-1 compute done
        if (ch + 1 < nch) { load_stage((ch + 1) & 1, ch + 1); CP_COMMIT(); }

        const int s = ch & 1;
        const uint32_t ab = smb + s * STAGE;
        const uint32_t hb = ab + STG_A;
        const uint32_t lb = hb + STG_A;

#pragma unroll
        for (int kt = 0; kt < 4; kt++) {
            const int ko = kt * 32;  // byte offset of k16 block
            uint32_t a[4][4];
#pragma unroll
            for (int mt = 0; mt < 4; mt++)
                ldm4(a[mt][0], a[mt][1], a[mt][2], a[mt][3],
                     ab + (wm * 64 + mt * 16 + arow) * RS + ko + ac8);

            uint32_t bh[8], bl[8];
#pragma unroll
            for (int p = 0; p < 2; p++) {
                ldm4(bh[p*4+0], bh[p*4+1], bh[p*4+2], bh[p*4+3],
                     hb + (wn * 32 + p * 16 + brow) * RS + ko + bc8);
                ldm4(bl[p*4+0], bl[p*4+1], bl[p*4+2], bl[p*4+3],
                     lb + (wn * 32 + p * 16 + brow) * RS + ko + bc8);
            }
            // all-hi then all-lo: 16 distinct accumulators per phase, no RAW stalls
#pragma unroll
            for (int g = 0; g < 4; g++) {
                int bi = (g >> 1) * 4 + (g & 1) * 2;
#pragma unroll
                for (int mt = 0; mt < 4; mt++)
                    mma16816(acc[mt][g], a[mt], bh[bi], bh[bi + 1]);
            }
#pragma unroll
            for (int g = 0; g < 4; g++) {
                int bi = (g >> 1) * 4 + (g & 1) * 2;
#pragma unroll
                for (int mt = 0; mt < 4; mt++)
                    mma16816(acc[mt][g], a[mt], bl[bi], bl[bi + 1]);
            }
        }
    }
    __syncthreads();

    // ---------------- epilogue ----------------
    if (!cm) {
#pragma unroll
        for (int mt = 0; mt < 4; mt++) {
#pragma unroll
            for (int g = 0; g < 4; g++) {
                int col = c0 + wn * 32 + g * 8 + (lane & 3) * 2;
                int row = n0 + wm * 64 + mt * 16 + (lane >> 2);
                float sA0 = Asc[col], sA1 = Asc[col + 1];
                float sB0 = Bsc[col], sB1 = Bsc[col + 1];
                float v00 = acc[mt][g][0] * sA0 + sB0;
                float v01 = acc[mt][g][1] * sA1 + sB1;
                float v10 = acc[mt][g][2] * sA0 + sB0;
                float v11 = acc[mt][g][3] * sA1 + sB1;
                if (Res) {
                    const float* r0 = Res + (long)tb * res_bs + (long)row * Mout + col;
                    float2 ra = *(const float2*)r0;
                    float2 rb = *(const float2*)(r0 + 8 * Mout);
                    v00 += ra.x; v01 += ra.y; v10 += rb.x; v11 += rb.y;
                }
                float* o0 = Out + (long)tb * out_bs + (long)row * Mout + col;
                float2 w0; w0.x = v00; w0.y = v01;
                float2 w1; w1.x = v10; w1.y = v11;
                *(float2*)o0 = w0;
                *(float2*)(o0 + 8 * Mout) = w1;
            }
        }
    } else {
        // stage through smem for coalesced channel-major stores
        float* sf = (float*)sm;
#pragma unroll
        for (int mt = 0; mt < 4; mt++) {
#pragma unroll
            for (int g = 0; g < 4; g++) {
                int cl = wn * 32 + g * 8 + (lane & 3) * 2;
                int rl = wm * 64 + mt * 16 + (lane >> 2);
                int col = c0 + cl, row = n0 + rl;
                float sA0 = Asc[col], sA1 = Asc[col + 1];
                float sB0 = Bsc[col], sB1 = Bsc[col + 1];
                float v00 = acc[mt][g][0] * sA0 + sB0;
                float v01 = acc[mt][g][1] * sA1 + sB1;
                float v10 = acc[mt][g][2] * sA0 + sB0;
                float v11 = acc[mt][g][3] * sA1 + sB1;
                const float* r0 = Res + (long)tb * res_bs + (long)row * Mout + col;
                float2 ra = *(const float2*)r0;
                float2 rb = *(const float2*)(r0 + 8 * Mout);
                v00 += ra.x; v01 += ra.y; v10 += rb.x; v11 += rb.y;
                sf[cl * 132 + rl]           = v00;
                sf[(cl + 1) * 132 + rl]     = v01;
                sf[cl * 132 + rl + 8]       = v10;
                sf[(cl + 1) * 132 + rl + 8] = v11;
            }
        }
        __syncthreads();
#pragma unroll
        for (int i = 0; i < 16; i++) {
            int c = wid * 16 + i;
            float* orow = Out + (long)tb * out_bs + (long)(c0 + c) * NN + n0;
#pragma unroll
            for (int j = 0; j < 4; j++)
                orow[lane + j * 32] = sf[c * 132 + lane + j * 32];
        }
    }
}

// ---------------- launch ----------------
extern "C" void kernel_launch(void* const* d_in, const int* in_sizes, int n_in,
                              void* d_out, int out_size)
{
    const float* x      = (const float*)d_in[0];
    const float* q_w    = (const float*)d_in[1];
    const float* k_w    = (const float*)d_in[2];
    const float* v_w    = (const float*)d_in[3];
    const float* proj_w = (const float*)d_in[4];
    const float* proj_b = (const float*)d_in[5];
    const float* fc1_w  = (const float*)d_in[6];
    const float* fc1_b  = (const float*)d_in[7];
    const float* fc2_w  = (const float*)d_in[8];
    const float* fc2_b  = (const float*)d_in[9];
    const float* q_bn   = (const float*)d_in[10];
    const float* k_bn   = (const float*)d_in[11];
    const float* v_bn   = (const float*)d_in[12];
    const float* proj_bn= (const float*)d_in[13];
    const float* fc1_bn = (const float*)d_in[14];
    const float* fc2_bn = (const float*)d_in[15];
    float* out = (float*)d_out;

    cudaFuncSetAttribute(mma_gemm, cudaFuncAttributeMaxDynamicSharedMemorySize, SMEM_TOT);

    float *p_xt, *p_q, *p_xat, *p_h1, *p_A, *p_Bc;
    __nv_bfloat16 *p_sx, *p_qs, *p_h1s, *p_whi, *p_wlo;
    cudaGetSymbolAddress((void**)&p_xt,  g_xt);
    cudaGetSymbolAddress((void**)&p_sx,  g_sx);
    cudaGetSymbolAddress((void**)&p_q,   g_q);
    cudaGetSymbolAddress((void**)&p_qs,  g_qs);
    cudaGetSymbolAddress((void**)&p_xat, g_xat);
    cudaGetSymbolAddress((void**)&p_h1,  g_h1);
    cudaGetSymbolAddress((void**)&p_h1s, g_h1s);
    cudaGetSymbolAddress((void**)&p_whi, g_whi);
    cudaGetSymbolAddress((void**)&p_wlo, g_wlo);
    cudaGetSymbolAddress((void**)&p_A,   g_A);
    cudaGetSymbolAddress((void**)&p_Bc,  g_Bc);

    // merged prep: BN fold + weight split + kvcnt zero
    prep_kernel<<<12434, 256>>>(q_bn, k_bn, v_bn, proj_bn, fc1_bn, fc2_bn,
                                proj_b, fc1_b, fc2_b,
                                q_w, k_w, v_w, proj_w, fc1_w, fc2_w);
    xpose_lif_kernel<<<dim3(8, 16, 16), dim3(32, 8)>>>(x);

    // qkv GEMM (Mout=1536 stacked)
    mma_gemm<<<dim3(2, 12, 64), 256, SMEM_TOT>>>(p_sx, (long)NN*CC, CC,
                                                 p_whi, p_wlo, W_QKV, CC,
                                                 p_A, p_Bc, nullptr, 0,
                                                 p_q, (long)NN*1536, 1536, 0);
    // LIF on qkv (4 elems/thread) + fused vh output
    lif4_kernel<<<6144, 256>>>((const float4*)p_q, (ushort4*)p_qs,
                               BB*NN*1536/4, (long)BB*NN*1536/4, 1.0f,
                               (float4*)(out + (long)TBCN));

    // kv counts (coalesced, exact int atomics) + talking-heads LIF + att
    kvcount_kernel<<<256, 256>>>();
    kvlif2_kernel<<<32, 256>>>();
    att_kernel<<<8192, 256>>>();

    // proj GEMM + BN + identity(x)
    mma_gemm<<<dim3(2, 4, 64), 256, SMEM_TOT>>>(p_qs, (long)NN*1536, 1536,
                                                p_whi, p_wlo, W_PROJ, CC,
                                                p_A + 1536, p_Bc + 1536, p_xt, (long)NN*CC,
                                                p_xat, (long)NN*CC, CC, 0);
    lif4_kernel<<<2048, 256>>>((const float4*)p_xat, (ushort4*)p_sx,
                               BB*NN*CC/4, (long)BB*NN*CC/4, 1.0f, nullptr);

    // fc1 GEMM
    mma_gemm<<<dim3(2, 16, 64), 256, SMEM_TOT>>>(p_sx, (long)NN*CC, CC,
                                                 p_whi, p_wlo, W_FC1, CC,
                                                 p_A + 2048, p_Bc + 2048, nullptr, 0,
                                                 p_h1, (long)NN*HID, HID, 0);
    lif4_kernel<<<8192, 256>>>((const float4*)p_h1, (ushort4*)p_h1s,
                               BB*NN*HID/4, (long)BB*NN*HID/4, 1.0f, nullptr);

    // fc2 GEMM + BN + idm(x_attn) -> d_out (channel-major, smem-staged)
    mma_gemm<<<dim3(2, 4, 64), 256, SMEM_TOT>>>(p_h1s, (long)NN*HID, HID,
                                                p_whi, p_wlo, W_FC2, HID,
                                                p_A + 4096, p_Bc + 4096, p_xat, (long)NN*CC,
                                                out, (long)CC*NN, CC, 1);
}

// round 12
// speedup vs baseline: 1.0704x; 1.0113x over previous
#include <cuda_runtime.h>
#include <cuda_bf16.h>
#include <cstdint>

// ---------------- problem constants ----------------
#define TT   4
#define BB   16
#define CC   512
#define NN   256
#define HID  2048
#define TBCN (TT*BB*CC*NN)     // 8,388,608

// ---------------- static scratch ----------------
__device__ float         g_xt  [64L*256*512];    // x transposed, channels-last fp32
__device__ __nv_bfloat16 g_sx  [64L*256*512];    // spikes (x / mlp), bf16
__device__ float         g_q   [64L*256*1536];   // qkv gemm out fp32 (channels-last)
__device__ __nv_bfloat16 g_qs  [64L*256*1536];   // qkv spikes bf16 (att in place in q cols)
__device__ float         g_xat [64L*256*512];    // attention block output fp32
__device__ float         g_h1  [64L*256*2048];   // fc1 out fp32
__device__ __nv_bfloat16 g_h1s [64L*256*2048];   // fc1 spikes bf16
__device__ __nv_bfloat16 g_kvs [64*512];         // kv spikes bf16
__device__ int           g_kvcnt[64*512];        // kv AND-counts (int, exact)
__device__ __nv_bfloat16 g_whi [3145728];        // weights hi bf16: qkv|proj|fc1|fc2
__device__ __nv_bfloat16 g_wlo [3145728];        // weights lo bf16
__device__ float         g_A   [4608];           // folded BN scale
__device__ float         g_Bc  [4608];           // folded BN bias

#define W_QKV  0L
#define W_PROJ 786432L
#define W_FC1  1048576L
#define W_FC2  2097152L

#define BF1 ((unsigned short)0x3F80)

// ---------------- PTX helpers (baseline ISA only) ----------------
__device__ __forceinline__ uint32_t smem_u32(const void* p) {
    uint32_t a;
    asm("{ .reg .u64 t; cvta.to.shared.u64 t, %1; cvt.u32.u64 %0, t; }" : "=r"(a) : "l"(p));
    return a;
}
__device__ __forceinline__ void cp16(uint32_t dst, const void* src) {
    asm volatile("cp.async.cg.shared.global [%0], [%1], 16;" :: "r"(dst), "l"(src));
}
#define CP_COMMIT() asm volatile("cp.async.commit_group;" ::: "memory")
#define CP_WAIT0()  asm volatile("cp.async.wait_group 0;" ::: "memory")

__device__ __forceinline__ void ldm4(uint32_t& r0, uint32_t& r1, uint32_t& r2, uint32_t& r3,
                                     uint32_t addr) {
    asm volatile("ldmatrix.sync.aligned.m8n8.x4.shared.b16 {%0,%1,%2,%3}, [%4];"
                 : "=r"(r0), "=r"(r1), "=r"(r2), "=r"(r3) : "r"(addr));
}
__device__ __forceinline__ void mma16816(float* c, const uint32_t* a, uint32_t b0, uint32_t b1) {
    asm volatile("mma.sync.aligned.m16n8k16.row.col.f32.bf16.bf16.f32 "
                 "{%0,%1,%2,%3}, {%4,%5,%6,%7}, {%8,%9}, {%0,%1,%2,%3};"
                 : "+f"(c[0]), "+f"(c[1]), "+f"(c[2]), "+f"(c[3])
                 : "r"(a[0]), "r"(a[1]), "r"(a[2]), "r"(a[3]), "r"(b0), "r"(b1));
}

// 2-CTA kernel smem: per stage A(128x144B) | Bhi(128x144B) | Blo(128x144B)
#define RS    144
#define STG_A (128*RS)        // 18432
#define STAGE (3*STG_A)       // 55296
#define SMEM_TOT (2*STAGE)    // 110592  (x2 CTAs/SM)

// 3-CTA (t3) kernel smem: per stage A(128x144B) | Bhi(64x144B) | Blo(64x144B)
#define STG_A3 (128*RS)       // 18432
#define STG_B3 (64*RS)        // 9216
#define STAGE3 (STG_A3 + 2*STG_B3)   // 36864
#define SMEM_T3 (2*STAGE3)    // 73728  (x3 CTAs/SM = 221184)

// ---------------- merged prep kernel ----------------
// blocks [0,18): BN fold; [18,12306): weight split; [12306,12434): zero kvcnt;
// [12434,14482): transpose+shortcut-LIF of x
__global__ void prep_kernel(const float* __restrict__ qbn, const float* __restrict__ kbn,
                            const float* __restrict__ vbn, const float* __restrict__ pbn,
                            const float* __restrict__ f1bn, const float* __restrict__ f2bn,
                            const float* __restrict__ pb, const float* __restrict__ f1b,
                            const float* __restrict__ f2b,
                            const float* __restrict__ qw, const float* __restrict__ kw,
                            const float* __restrict__ vw, const float* __restrict__ pj,
                            const float* __restrict__ f1, const float* __restrict__ f2,
                            const float* __restrict__ x)
{
    int blk = blockIdx.x;
    if (blk < 18) {
        int i = blk * 256 + threadIdx.x;
        if (i >= 4608) return;
        const float* bn; int c; int nc; float bias = 0.f;
        if (i < 1536)      { int s = i >> 9; c = i & 511; nc = CC;
                             bn = (s == 0) ? qbn : (s == 1) ? kbn : vbn; }
        else if (i < 2048) { c = i - 1536; nc = CC;  bn = pbn;  bias = pb[c]; }
        else if (i < 4096) { c = i - 2048; nc = HID; bn = f1bn; bias = f1b[c]; }
        else               { c = i - 4096; nc = CC;  bn = f2bn; bias = f2b[c]; }
        float g  = bn[c];
        float be = bn[nc + c];
        float m  = bn[2*nc + c];
        float v  = bn[3*nc + c];
        float a  = g / sqrtf(v + 1e-5f);
        g_A[i]  = a;
        g_Bc[i] = be + (bias - m) * a;
    } else if (blk < 12306) {
        long i = (long)(blk - 18) * 256 + threadIdx.x;
        if (i >= 3145728L) return;
        float w;
        if (i < 786432L)       { long s = i / 262144L, r = i % 262144L;
                                 w = (s == 0) ? qw[r] : (s == 1) ? kw[r] : vw[r]; }
        else if (i < 1048576L) w = pj[i - 786432L];
        else if (i < 2097152L) w = f1[i - 1048576L];
        else                   w = f2[i - 2097152L];
        __nv_bfloat16 h = __float2bfloat16(w);
        g_whi[i] = h;
        g_wlo[i] = __float2bfloat16(w - __bfloat162float(h));
    } else if (blk < 12434) {
        int i = (blk - 12306) * 256 + threadIdx.x;
        g_kvcnt[i] = 0;
    } else {
        // transpose + shortcut LIF
        __shared__ float t4[4][32][33];
        int idx = blk - 12434;               // 0..2047
        int n0 = (idx & 7) * 32;
        int c0 = ((idx >> 3) & 15) * 32;
        int b  = idx >> 7;
        int tx = threadIdx.x & 31, ty = threadIdx.x >> 5;   // (32,8)
#pragma unroll
        for (int t = 0; t < TT; t++)
#pragma unroll
            for (int i = 0; i < 4; i++) {
                int c = c0 + ty + i * 8;
                t4[t][ty + i * 8][tx] = x[(((long)t * BB + b) * CC + c) * NN + n0 + tx];
            }
        __syncthreads();
#pragma unroll
        for (int i = 0; i < 4; i++) {
            int n = n0 + ty + i * 8;
            int c = c0 + tx;
            float v = 0.f;
#pragma unroll
            for (int t = 0; t < TT; t++) {
                float xv = t4[t][tx][ty + i * 8];
                long o = (((long)t * BB + b) * NN + n) * CC + c;
                g_xt[o] = xv;
                v = 0.5f * (v + xv);
                bool sp = (v >= 1.0f);
                g_sx[o] = __float2bfloat16(sp ? 1.f : 0.f);
                if (sp) v = 0.f;
            }
        }
    }
}

// vectorized LIF: 4 elems/thread, fp32 in -> bf16 spikes out.
// If vhout != nullptr (qkv path), threads covering v-channels also write fp32 vh.
__global__ void lif4_kernel(const float4* __restrict__ in, ushort4* __restrict__ out,
                            int n4, long t4stride, float vth, float4* __restrict__ vhout)
{
    int i = blockIdx.x * 256 + threadIdx.x;
    if (i >= n4) return;

    int c4 = i % 384;
    int n  = (i / 384) & 255;
    int b  = i / 98304;
    bool do_vh = (vhout != nullptr) && (c4 >= 256);
    int ch4 = c4 - 256;
    int h   = ch4 >> 4;
    int vbase = 0;
    if (do_vh) vbase = n * 16 + (ch4 & 15);

    float vx = 0.f, vy = 0.f, vz = 0.f, vw = 0.f;
#pragma unroll
    for (int t = 0; t < TT; t++) {
        float4 xv = in[(long)t * t4stride + i];
        ushort4 s;
        vx = 0.5f * (vx + xv.x); s.x = (vx >= vth) ? BF1 : 0; if (vx >= vth) vx = 0.f;
        vy = 0.5f * (vy + xv.y); s.y = (vy >= vth) ? BF1 : 0; if (vy >= vth) vy = 0.f;
        vz = 0.5f * (vz + xv.z); s.z = (vz >= vth) ? BF1 : 0; if (vz >= vth) vz = 0.f;
        vw = 0.5f * (vw + xv.w); s.w = (vw >= vth) ? BF1 : 0; if (vw >= vth) vw = 0.f;
        out[(long)t * t4stride + i] = s;
        if (do_vh) {
            float4 o;
            o.x = s.x ? 1.f : 0.f;
            o.y = s.y ? 1.f : 0.f;
            o.z = s.z ? 1.f : 0.f;
            o.w = s.w ? 1.f : 0.f;
            vhout[((long)((t * BB + b) * 8 + h)) * 4096 + vbase] = o;
        }
    }
}

// coalesced kv AND-count
__global__ void kvcount_kernel()
{
    int tb = blockIdx.x >> 2;
    int ng = blockIdx.x & 3;
    int t  = threadIdx.x;
    const unsigned int* qs = (const unsigned int*)g_qs;
    long base = (long)tb * 256 * 768;
    int c0 = 0, c1 = 0;
#pragma unroll 8
    for (int n = ng * 64; n < ng * 64 + 64; n++) {
        unsigned int k = qs[base + (long)n * 768 + 256 + t];
        unsigned int v = qs[base + (long)n * 768 + 512 + t];
        unsigned int a = k & v;
        c0 += (a & 0xFFFFu) ? 1 : 0;
        c1 += (a >> 16)     ? 1 : 0;
    }
    atomicAdd(&g_kvcnt[tb * 512 + 2 * t],     c0);
    atomicAdd(&g_kvcnt[tb * 512 + 2 * t + 1], c1);
}

// talking-heads LIF over counts (vth=0.5)
__global__ void kvlif2_kernel()
{
    int idx = blockIdx.x * 256 + threadIdx.x;
    int b = idx >> 9, c = idx & 511;
    float v = 0.f;
#pragma unroll
    for (int t = 0; t < TT; t++) {
        int tb = t * BB + b;
        float s = (float)g_kvcnt[tb * 512 + c];
        v = 0.5f * (v + s);
        bool sp = (v >= 0.5f);
        g_kvs[tb * 512 + c] = __float2bfloat16(sp ? 1.f : 0.f);
        if (sp) v = 0.f;
    }
}

// att = q & kv (bitwise over bf16 spike lanes), in place
__global__ void att_kernel()
{
    long i = (long)blockIdx.x * 256 + threadIdx.x;
    int c4 = (int)(i & 127);
    int n  = (int)((i >> 7) & 255);
    int tb = (int)(i >> 15);
    long qq = (((long)tb * 256 + n) * 1536 + c4 * 4) >> 2;
    uint2 q = ((uint2*)g_qs)[qq];
    uint2 kv = ((const uint2*)g_kvs)[((long)tb * 512 + c4 * 4) >> 2];
    q.x &= kv.x; q.y &= kv.y;
    ((uint2*)g_qs)[qq] = q;
}

// ---------------- HMMA GEMM (2 CTAs/SM, 256 thr) ----------------
__global__ void __launch_bounds__(256, 2)
mma_gemm(const __nv_bfloat16* __restrict__ A, long a_bs, int lda,
         const __nv_bfloat16* __restrict__ Whi, const __nv_bfloat16* __restrict__ Wlo,
         long wbase, int K,
         const float* __restrict__ Asc, const float* __restrict__ Bsc,
         const float* __restrict__ Res, long res_bs,
         float* __restrict__ Out, long out_bs, int Mout, int cm)
{
    extern __shared__ char sm[];
    const uint32_t smb = smem_u32(sm);

    const int tid  = threadIdx.x;
    const int lane = tid & 31;
    const int wid  = tid >> 5;
    const int wm   = wid & 1;
    const int wn   = wid >> 1;
    const int n0   = blockIdx.x * 128;
    const int c0   = blockIdx.y * 128;
    const int tb   = blockIdx.z;
    const int nch  = K >> 6;

    const __nv_bfloat16* Ab = A + (long)tb * a_bs + (long)n0 * lda;
    const __nv_bfloat16* Hb = Whi + wbase + (long)c0 * K;
    const __nv_bfloat16* Lb = Wlo + wbase + (long)c0 * K;

    const int arow = (lane & 7) + ((lane >> 3) & 1) * 8;
    const int ac8  = (lane >> 4) * 16;
    const int brow = (lane & 7) + (lane >> 4) * 8;
    const int bc8  = ((lane >> 3) & 1) * 16;

    float acc[4][4][4];
#pragma unroll
    for (int a_ = 0; a_ < 4; a_++)
#pragma unroll
        for (int b_ = 0; b_ < 4; b_++)
#pragma unroll
            for (int r_ = 0; r_ < 4; r_++) acc[a_][b_][r_] = 0.f;

    auto load_stage = [&](int s, int kc) {
        uint32_t base = smb + s * STAGE;
#pragma unroll
        for (int jj = 0; jj < 4; jj++) {
            int u = jj * 256 + tid;
            int r = u >> 3, c16 = u & 7;
            cp16(base + r * RS + c16 * 16, Ab + (long)r * lda + kc * 64 + c16 * 8);
        }
#pragma unroll
        for (int jj = 0; jj < 4; jj++) {
            int u = jj * 256 + tid;
            int r = u >> 3, c16 = u & 7;
            cp16(base + STG_A + r * RS + c16 * 16, Hb + (long)r * K + kc * 64 + c16 * 8);
        }
#pragma unroll
        for (int jj = 0; jj < 4; jj++) {
            int u = jj * 256 + tid;
            int r = u >> 3, c16 = u & 7;
            cp16(base + 2 * STG_A + r * RS + c16 * 16, Lb + (long)r * K + kc * 64 + c16 * 8);
        }
    };

    load_stage(0, 0);
    CP_COMMIT();

    for (int ch = 0; ch < nch; ch++) {
        CP_WAIT0();
        __syncthreads();
        if (ch + 1 < nch) { load_stage((ch + 1) & 1, ch + 1); CP_COMMIT(); }

        const int s = ch & 1;
        const uint32_t ab = smb + s * STAGE;
        const uint32_t hb = ab + STG_A;
        const uint32_t lb = hb + STG_A;

#pragma unroll
        for (int kt = 0; kt < 4; kt++) {
            const int ko = kt * 32;
            uint32_t a[4][4];
#pragma unroll
            for (int mt = 0; mt < 4; mt++)
                ldm4(a[mt][0], a[mt][1], a[mt][2], a[mt][3],
                     ab + (wm * 64 + mt * 16 + arow) * RS + ko + ac8);

            uint32_t bh[8], bl[8];
#pragma unroll
            for (int p = 0; p < 2; p++)
                ldm4(bh[p*4+0], bh[p*4+1], bh[p*4+2], bh[p*4+3],
                     hb + (wn * 32 + p * 16 + brow) * RS + ko + bc8);

            // hi MMAs g=0,1 while bl loads are issued (hide LDSM latency)
#pragma unroll
            for (int g = 0; g < 2; g++) {
                int bi = (g >> 1) * 4 + (g & 1) * 2;
#pragma unroll
                for (int mt = 0; mt < 4; mt++)
                    mma16816(acc[mt][g], a[mt], bh[bi], bh[bi + 1]);
            }
#pragma unroll
            for (int p = 0; p < 2; p++)
                ldm4(bl[p*4+0], bl[p*4+1], bl[p*4+2], bl[p*4+3],
                     lb + (wn * 32 + p * 16 + brow) * RS + ko + bc8);
#pragma unroll
            for (int g = 2; g < 4; g++) {
                int bi = (g >> 1) * 4 + (g & 1) * 2;
#pragma unroll
                for (int mt = 0; mt < 4; mt++)
                    mma16816(acc[mt][g], a[mt], bh[bi], bh[bi + 1]);
            }
#pragma unroll
            for (int g = 0; g < 4; g++) {
                int bi = (g >> 1) * 4 + (g & 1) * 2;
#pragma unroll
                for (int mt = 0; mt < 4; mt++)
                    mma16816(acc[mt][g], a[mt], bl[bi], bl[bi + 1]);
            }
        }
    }
    __syncthreads();

    // ---------------- epilogue ----------------
    if (!cm) {
#pragma unroll
        for (int mt = 0; mt < 4; mt++) {
#pragma unroll
            for (int g = 0; g < 4; g++) {
                int col = c0 + wn * 32 + g * 8 + (lane & 3) * 2;
                int row = n0 + wm * 64 + mt * 16 + (lane >> 2);
                float sA0 = Asc[col], sA1 = Asc[col + 1];
                float sB0 = Bsc[col], sB1 = Bsc[col + 1];
                float v00 = acc[mt][g][0] * sA0 + sB0;
                float v01 = acc[mt][g][1] * sA1 + sB1;
                float v10 = acc[mt][g][2] * sA0 + sB0;
                float v11 = acc[mt][g][3] * sA1 + sB1;
                if (Res) {
                    const float* r0 = Res + (long)tb * res_bs + (long)row * Mout + col;
                    float2 ra = *(const float2*)r0;
                    float2 rb = *(const float2*)(r0 + 8 * Mout);
                    v00 += ra.x; v01 += ra.y; v10 += rb.x; v11 += rb.y;
                }
                float* o0 = Out + (long)tb * out_bs + (long)row * Mout + col;
                float2 w0; w0.x = v00; w0.y = v01;
                float2 w1; w1.x = v10; w1.y = v11;
                *(float2*)o0 = w0;
                *(float2*)(o0 + 8 * Mout) = w1;
            }
        }
    } else {
        float* sf = (float*)sm;
#pragma unroll
        for (int mt = 0; mt < 4; mt++) {
#pragma unroll
            for (int g = 0; g < 4; g++) {
                int cl = wn * 32 + g * 8 + (lane & 3) * 2;
                int rl = wm * 64 + mt * 16 + (lane >> 2);
                int col = c0 + cl, row = n0 + rl;
                float sA0 = Asc[col], sA1 = Asc[col + 1];
                float sB0 = Bsc[col], sB1 = Bsc[col + 1];
                float v00 = acc[mt][g][0] * sA0 + sB0;
                float v01 = acc[mt][g][1] * sA1 + sB1;
                float v10 = acc[mt][g][2] * sA0 + sB0;
                float v11 = acc[mt][g][3] * sA1 + sB1;
                const float* r0 = Res + (long)tb * res_bs + (long)row * Mout + col;
                float2 ra = *(const float2*)r0;
                float2 rb = *(const float2*)(r0 + 8 * Mout);
                v00 += ra.x; v01 += ra.y; v10 += rb.x; v11 += rb.y;
                sf[cl * 132 + rl]           = v00;
                sf[(cl + 1) * 132 + rl]     = v01;
                sf[cl * 132 + rl + 8]       = v10;
                sf[(cl + 1) * 132 + rl + 8] = v11;
            }
        }
        __syncthreads();
#pragma unroll
        for (int i = 0; i < 16; i++) {
            int c = wid * 16 + i;
            float* orow = Out + (long)tb * out_bs + (long)(c0 + c) * NN + n0;
#pragma unroll
            for (int j = 0; j < 4; j++)
                orow[lane + j * 32] = sf[c * 132 + lane + j * 32];
        }
    }
}

// ---------------- HMMA GEMM t3 (3 CTAs/SM, 128 thr, tile 128x64) ----------------
// qkv only: no residual, no cm. 4 warps (wm 2 x wn 2), warp tile 64x32.
__global__ void __launch_bounds__(128, 3)
mma_gemm_t3(const __nv_bfloat16* __restrict__ A, long a_bs, int lda,
            const __nv_bfloat16* __restrict__ Whi, const __nv_bfloat16* __restrict__ Wlo,
            long wbase, int K,
            const float* __restrict__ Asc, const float* __restrict__ Bsc,
            float* __restrict__ Out, long out_bs, int Mout)
{
    extern __shared__ char sm[];
    const uint32_t smb = smem_u32(sm);

    const int tid  = threadIdx.x;
    const int lane = tid & 31;
    const int wid  = tid >> 5;          // 4 warps
    const int wm   = wid & 1;
    const int wn   = wid >> 1;          // 0,1
    const int n0   = blockIdx.x * 128;
    const int c0   = blockIdx.y * 64;
    const int tb   = blockIdx.z;
    const int nch  = K >> 6;

    const __nv_bfloat16* Ab = A + (long)tb * a_bs + (long)n0 * lda;
    const __nv_bfloat16* Hb = Whi + wbase + (long)c0 * K;
    const __nv_bfloat16* Lb = Wlo + wbase + (long)c0 * K;

    const int arow = (lane & 7) + ((lane >> 3) & 1) * 8;
    const int ac8  = (lane >> 4) * 16;
    const int brow = (lane & 7) + (lane >> 4) * 8;
    const int bc8  = ((lane >> 3) & 1) * 16;

    float acc[4][4][4];
#pragma unroll
    for (int a_ = 0; a_ < 4; a_++)
#pragma unroll
        for (int b_ = 0; b_ < 4; b_++)
#pragma unroll
            for (int r_ = 0; r_ < 4; r_++) acc[a_][b_][r_] = 0.f;

    auto load_stage = [&](int s, int kc) {
        uint32_t base = smb + s * STAGE3;
#pragma unroll
        for (int jj = 0; jj < 8; jj++) {
            int u = jj * 128 + tid;           // 0..1023 (A: 128 rows)
            int r = u >> 3, c16 = u & 7;
            cp16(base + r * RS + c16 * 16, Ab + (long)r * lda + kc * 64 + c16 * 8);
        }
#pragma unroll
        for (int jj = 0; jj < 4; jj++) {
            int u = jj * 128 + tid;           // 0..511 (B: 64 rows)
            int r = u >> 3, c16 = u & 7;
            cp16(base + STG_A3 + r * RS + c16 * 16, Hb + (long)r * K + kc * 64 + c16 * 8);
        }
#pragma unroll
        for (int jj = 0; jj < 4; jj++) {
            int u = jj * 128 + tid;
            int r = u >> 3, c16 = u & 7;
            cp16(base + STG_A3 + STG_B3 + r * RS + c16 * 16,
                 Lb + (long)r * K + kc * 64 + c16 * 8);
        }
    };

    load_stage(0, 0);
    CP_COMMIT();

    for (int ch = 0; ch < nch; ch++) {
        CP_WAIT0();
        __syncthreads();
        if (ch + 1 < nch) { load_stage((ch + 1) & 1, ch + 1); CP_COMMIT(); }

        const int s = ch & 1;
        const uint32_t ab = smb + s * STAGE3;
        const uint32_t hb = ab + STG_A3;
        const uint32_t lb = hb + STG_B3;

#pragma unroll
        for (int kt = 0; kt < 4; kt++) {
            const int ko = kt * 32;
            uint32_t a[4][4];
#pragma unroll
            for (int mt = 0; mt < 4; mt++)
                ldm4(a[mt][0], a[mt][1], a[mt][2], a[mt][3],
                     ab + (wm * 64 + mt * 16 + arow) * RS + ko + ac8);

            uint32_t bh[8], bl[8];
#pragma unroll
            for (int p = 0; p < 2; p++)
                ldm4(bh[p*4+0], bh[p*4+1], bh[p*4+2], bh[p*4+3],
                     hb + (wn * 32 + p * 16 + brow) * RS + ko + bc8);
#pragma unroll
            for (int g = 0; g < 2; g++) {
                int bi = (g >> 1) * 4 + (g & 1) * 2;
#pragma unroll
                for (int mt = 0; mt < 4; mt++)
                    mma16816(acc[mt][g], a[mt], bh[bi], bh[bi + 1]);
            }
#pragma unroll
            for (int p = 0; p < 2; p++)
                ldm4(bl[p*4+0], bl[p*4+1], bl[p*4+2], bl[p*4+3],
                     lb + (wn * 32 + p * 16 + brow) * RS + ko + bc8);
#pragma unroll
            for (int g = 2; g < 4; g++) {
                int bi = (g >> 1) * 4 + (g & 1) * 2;
#pragma unroll
                for (int mt = 0; mt < 4; mt++)
                    mma16816(acc[mt][g], a[mt], bh[bi], bh[bi + 1]);
            }
#pragma unroll
            for (int g = 0; g < 4; g++) {
                int bi = (g >> 1) * 4 + (g & 1) * 2;
#pragma unroll
                for (int mt = 0; mt < 4; mt++)
                    mma16816(acc[mt][g], a[mt], bl[bi], bl[bi + 1]);
            }
        }
    }

    // epilogue (non-cm, no residual)
#pragma unroll
    for (int mt = 0; mt < 4; mt++) {
#pragma unroll
        for (int g = 0; g < 4; g++) {
            int col = c0 + wn * 32 + g * 8 + (lane & 3) * 2;
            int row = n0 + wm * 64 + mt * 16 + (lane >> 2);
            float sA0 = Asc[col], sA1 = Asc[col + 1];
            float sB0 = Bsc[col], sB1 = Bsc[col + 1];
            float2 w0, w1;
            w0.x = acc[mt][g][0] * sA0 + sB0;
            w0.y = acc[mt][g][1] * sA1 + sB1;
            w1.x = acc[mt][g][2] * sA0 + sB0;
            w1.y = acc[mt][g][3] * sA1 + sB1;
            float* o0 = Out + (long)tb * out_bs + (long)row * Mout + col;
            *(float2*)o0 = w0;
            *(float2*)(o0 + 8 * Mout) = w1;
        }
    }
}

// ---------------- launch ----------------
extern "C" void kernel_launch(void* const* d_in, const int* in_sizes, int n_in,
                              void* d_out, int out_size)
{
    const float* x      = (const float*)d_in[0];
    const float* q_w    = (const float*)d_in[1];
    const float* k_w    = (const float*)d_in[2];
    const float* v_w    = (const float*)d_in[3];
    const float* proj_w = (const float*)d_in[4];
    const float* proj_b = (const float*)d_in[5];
    const float* fc1_w  = (const float*)d_in[6];
    const float* fc1_b  = (const float*)d_in[7];
    const float* fc2_w  = (const float*)d_in[8];
    const float* fc2_b  = (const float*)d_in[9];
    const float* q_bn   = (const float*)d_in[10];
    const float* k_bn   = (const float*)d_in[11];
    const float* v_bn   = (const float*)d_in[12];
    const float* proj_bn= (const float*)d_in[13];
    const float* fc1_bn = (const float*)d_in[14];
    const float* fc2_bn = (const float*)d_in[15];
    float* out = (float*)d_out;

    cudaFuncSetAttribute(mma_gemm,    cudaFuncAttributeMaxDynamicSharedMemorySize, SMEM_TOT);
    cudaFuncSetAttribute(mma_gemm_t3, cudaFuncAttributeMaxDynamicSharedMemorySize, SMEM_T3);

    float *p_xt, *p_q, *p_xat, *p_h1, *p_A, *p_Bc;
    __nv_bfloat16 *p_sx, *p_qs, *p_h1s, *p_whi, *p_wlo;
    cudaGetSymbolAddress((void**)&p_xt,  g_xt);
    cudaGetSymbolAddress((void**)&p_sx,  g_sx);
    cudaGetSymbolAddress((void**)&p_q,   g_q);
    cudaGetSymbolAddress((void**)&p_qs,  g_qs);
    cudaGetSymbolAddress((void**)&p_xat, g_xat);
    cudaGetSymbolAddress((void**)&p_h1,  g_h1);
    cudaGetSymbolAddress((void**)&p_h1s, g_h1s);
    cudaGetSymbolAddress((void**)&p_whi, g_whi);
    cudaGetSymbolAddress((void**)&p_wlo, g_wlo);
    cudaGetSymbolAddress((void**)&p_A,   g_A);
    cudaGetSymbolAddress((void**)&p_Bc,  g_Bc);

    // merged prep: BN fold + weight split + kvcnt zero + transpose/LIF of x
    prep_kernel<<<14482, 256>>>(q_bn, k_bn, v_bn, proj_bn, fc1_bn, fc2_bn,
                                proj_b, fc1_b, fc2_b,
                                q_w, k_w, v_w, proj_w, fc1_w, fc2_w, x);

    // qkv GEMM (Mout=1536), 3-CTA/SM variant: grid 2 x 24 x 64
    mma_gemm_t3<<<dim3(2, 24, 64), 128, SMEM_T3>>>(p_sx, (long)NN*CC, CC,
                                                   p_whi, p_wlo, W_QKV, CC,
                                                   p_A, p_Bc,
                                                   p_q, (long)NN*1536, 1536);
    // LIF on qkv + fused vh output
    lif4_kernel<<<6144, 256>>>((const float4*)p_q, (ushort4*)p_qs,
                               BB*NN*1536/4, (long)BB*NN*1536/4, 1.0f,
                               (float4*)(out + (long)TBCN));

    kvcount_kernel<<<256, 256>>>();
    kvlif2_kernel<<<32, 256>>>();
    att_kernel<<<8192, 256>>>();

    // proj GEMM + BN + identity(x)
    mma_gemm<<<dim3(2, 4, 64), 256, SMEM_TOT>>>(p_qs, (long)NN*1536, 1536,
                                                p_whi, p_wlo, W_PROJ, CC,
                                                p_A + 1536, p_Bc + 1536, p_xt, (long)NN*CC,
                                                p_xat, (long)NN*CC, CC, 0);
    lif4_kernel<<<2048, 256>>>((const float4*)p_xat, (ushort4*)p_sx,
                               BB*NN*CC/4, (long)BB*NN*CC/4, 1.0f, nullptr);

    // fc1 GEMM
    mma_gemm<<<dim3(2, 16, 64), 256, SMEM_TOT>>>(p_sx, (long)NN*CC, CC,
                                                 p_whi, p_wlo, W_FC1, CC,
                                                 p_A + 2048, p_Bc + 2048, nullptr, 0,
                                                 p_h1, (long)NN*HID, HID, 0);
    lif4_kernel<<<8192, 256>>>((const float4*)p_h1, (ushort4*)p_h1s,
                               BB*NN*HID/4, (long)BB*NN*HID/4, 1.0f, nullptr);

    // fc2 GEMM + BN + idm(x_attn) -> d_out (channel-major, smem-staged)
    mma_gemm<<<dim3(2, 4, 64), 256, SMEM_TOT>>>(p_h1s, (long)NN*HID, HID,
                                                p_whi, p_wlo, W_FC2, HID,
                                                p_A + 4096, p_Bc + 4096, p_xat, (long)NN*CC,
                                                out, (long)CC*NN, CC, 1);
}

// round 13
// speedup vs baseline: 1.1136x; 1.0403x over previous
#include <cuda_runtime.h>
#include <cuda_bf16.h>
#include <cstdint>

// ---------------- problem constants ----------------
#define TT   4
#define BB   16
#define CC   512
#define NN   256
#define HID  2048
#define TBCN (TT*BB*CC*NN)     // 8,388,608

// ---------------- static scratch ----------------
__device__ float         g_xt  [64L*256*512];    // x transposed, channels-last fp32
__device__ __nv_bfloat16 g_sx  [64L*256*512];    // spikes (x / mlp), bf16
__device__ __nv_bfloat16 g_qs  [64L*256*1536];   // qkv spikes bf16 (att in place in q cols)
__device__ float         g_xat [64L*256*512];    // attention block output fp32
__device__ __nv_bfloat16 g_h1s [64L*256*2048];   // fc1 spikes bf16
__device__ __nv_bfloat16 g_kvs [64*512];         // kv spikes bf16
__device__ int           g_kvcnt[64*512];        // kv AND-counts (int, exact)
__device__ __nv_bfloat16 g_whi [3145728];        // weights hi bf16: qkv|proj|fc1|fc2
__device__ __nv_bfloat16 g_wlo [3145728];        // weights lo bf16
__device__ float         g_A   [4608];           // folded BN scale
__device__ float         g_Bc  [4608];           // folded BN bias

#define W_QKV  0L
#define W_PROJ 786432L
#define W_FC1  1048576L
#define W_FC2  2097152L

#define BF1 ((unsigned short)0x3F80)

// ---------------- PTX helpers (baseline ISA only) ----------------
__device__ __forceinline__ uint32_t smem_u32(const void* p) {
    uint32_t a;
    asm("{ .reg .u64 t; cvta.to.shared.u64 t, %1; cvt.u32.u64 %0, t; }" : "=r"(a) : "l"(p));
    return a;
}
__device__ __forceinline__ void cp16(uint32_t dst, const void* src) {
    asm volatile("cp.async.cg.shared.global [%0], [%1], 16;" :: "r"(dst), "l"(src));
}
#define CP_COMMIT() asm volatile("cp.async.commit_group;" ::: "memory")
#define CP_WAIT0()  asm volatile("cp.async.wait_group 0;" ::: "memory")

__device__ __forceinline__ void ldm4(uint32_t& r0, uint32_t& r1, uint32_t& r2, uint32_t& r3,
                                     uint32_t addr) {
    asm volatile("ldmatrix.sync.aligned.m8n8.x4.shared.b16 {%0,%1,%2,%3}, [%4];"
                 : "=r"(r0), "=r"(r1), "=r"(r2), "=r"(r3) : "r"(addr));
}
__device__ __forceinline__ void mma16816(float* c, const uint32_t* a, uint32_t b0, uint32_t b1) {
    asm volatile("mma.sync.aligned.m16n8k16.row.col.f32.bf16.bf16.f32 "
                 "{%0,%1,%2,%3}, {%4,%5,%6,%7}, {%8,%9}, {%0,%1,%2,%3};"
                 : "+f"(c[0]), "+f"(c[1]), "+f"(c[2]), "+f"(c[3])
                 : "r"(a[0]), "r"(a[1]), "r"(a[2]), "r"(a[3]), "r"(b0), "r"(b1));
}

// SMEM: per stage A(128x144B) | Bhi(128x144B) | Blo(128x144B); 2 stages; K-chunk 64
#define RS    144
#define STG_A (128*RS)        // 18432
#define STAGE (3*STG_A)       // 55296
#define SMEM_TOT (2*STAGE)    // 110592  (x2 CTAs/SM)

// ---------------- merged prep kernel ----------------
// blocks [0,18): BN fold; [18,12306): weight split; [12306,12434): zero kvcnt;
// [12434,14482): transpose + shortcut LIF of x
__global__ void prep_kernel(const float* __restrict__ qbn, const float* __restrict__ kbn,
                            const float* __restrict__ vbn, const float* __restrict__ pbn,
                            const float* __restrict__ f1bn, const float* __restrict__ f2bn,
                            const float* __restrict__ pb, const float* __restrict__ f1b,
                            const float* __restrict__ f2b,
                            const float* __restrict__ qw, const float* __restrict__ kw,
                            const float* __restrict__ vw, const float* __restrict__ pj,
                            const float* __restrict__ f1, const float* __restrict__ f2,
                            const float* __restrict__ x)
{
    int blk = blockIdx.x;
    if (blk < 18) {
        int i = blk * 256 + threadIdx.x;
        if (i >= 4608) return;
        const float* bn; int c; int nc; float bias = 0.f;
        if (i < 1536)      { int s = i >> 9; c = i & 511; nc = CC;
                             bn = (s == 0) ? qbn : (s == 1) ? kbn : vbn; }
        else if (i < 2048) { c = i - 1536; nc = CC;  bn = pbn;  bias = pb[c]; }
        else if (i < 4096) { c = i - 2048; nc = HID; bn = f1bn; bias = f1b[c]; }
        else               { c = i - 4096; nc = CC;  bn = f2bn; bias = f2b[c]; }
        float g  = bn[c];
        float be = bn[nc + c];
        float m  = bn[2*nc + c];
        float v  = bn[3*nc + c];
        float a  = g / sqrtf(v + 1e-5f);
        g_A[i]  = a;
        g_Bc[i] = be + (bias - m) * a;
    } else if (blk < 12306) {
        long i = (long)(blk - 18) * 256 + threadIdx.x;
        if (i >= 3145728L) return;
        float w;
        if (i < 786432L)       { long s = i / 262144L, r = i % 262144L;
                                 w = (s == 0) ? qw[r] : (s == 1) ? kw[r] : vw[r]; }
        else if (i < 1048576L) w = pj[i - 786432L];
        else if (i < 2097152L) w = f1[i - 1048576L];
        else                   w = f2[i - 2097152L];
        __nv_bfloat16 h = __float2bfloat16(w);
        g_whi[i] = h;
        g_wlo[i] = __float2bfloat16(w - __bfloat162float(h));
    } else if (blk < 12434) {
        int i = (blk - 12306) * 256 + threadIdx.x;
        g_kvcnt[i] = 0;
    } else {
        __shared__ float t4[4][32][33];
        int idx = blk - 12434;
        int n0 = (idx & 7) * 32;
        int c0 = ((idx >> 3) & 15) * 32;
        int b  = idx >> 7;
        int tx = threadIdx.x & 31, ty = threadIdx.x >> 5;
#pragma unroll
        for (int t = 0; t < TT; t++)
#pragma unroll
            for (int i = 0; i < 4; i++) {
                int c = c0 + ty + i * 8;
                t4[t][ty + i * 8][tx] = x[(((long)t * BB + b) * CC + c) * NN + n0 + tx];
            }
        __syncthreads();
#pragma unroll
        for (int i = 0; i < 4; i++) {
            int n = n0 + ty + i * 8;
            int c = c0 + tx;
            float v = 0.f;
#pragma unroll
            for (int t = 0; t < TT; t++) {
                float xv = t4[t][tx][ty + i * 8];
                long o = (((long)t * BB + b) * NN + n) * CC + c;
                g_xt[o] = xv;
                v = 0.5f * (v + xv);
                bool sp = (v >= 1.0f);
                g_sx[o] = __float2bfloat16(sp ? 1.f : 0.f);
                if (sp) v = 0.f;
            }
        }
    }
}

// coalesced kv AND-count (more parallelism: 1024 blocks, 16 n-rows each)
__global__ void kvcount_kernel()
{
    int tb = blockIdx.x >> 4;
    int ng = blockIdx.x & 15;
    int t  = threadIdx.x;
    const unsigned int* qs = (const unsigned int*)g_qs;
    long base = (long)tb * 256 * 768;
    int c0 = 0, c1 = 0;
#pragma unroll 8
    for (int n = ng * 16; n < ng * 16 + 16; n++) {
        unsigned int k = qs[base + (long)n * 768 + 256 + t];
        unsigned int v = qs[base + (long)n * 768 + 512 + t];
        unsigned int a = k & v;
        c0 += (a & 0xFFFFu) ? 1 : 0;
        c1 += (a >> 16)     ? 1 : 0;
    }
    atomicAdd(&g_kvcnt[tb * 512 + 2 * t],     c0);
    atomicAdd(&g_kvcnt[tb * 512 + 2 * t + 1], c1);
}

// talking-heads LIF over counts (vth=0.5)
__global__ void kvlif2_kernel()
{
    int idx = blockIdx.x * 256 + threadIdx.x;
    int b = idx >> 9, c = idx & 511;
    float v = 0.f;
#pragma unroll
    for (int t = 0; t < TT; t++) {
        int tb = t * BB + b;
        float s = (float)g_kvcnt[tb * 512 + c];
        v = 0.5f * (v + s);
        bool sp = (v >= 0.5f);
        g_kvs[tb * 512 + c] = __float2bfloat16(sp ? 1.f : 0.f);
        if (sp) v = 0.f;
    }
}

// att = q & kv (bitwise over bf16 spike lanes), in place
__global__ void att_kernel()
{
    long i = (long)blockIdx.x * 256 + threadIdx.x;
    int c4 = (int)(i & 127);
    int n  = (int)((i >> 7) & 255);
    int tb = (int)(i >> 15);
    long qq = (((long)tb * 256 + n) * 1536 + c4 * 4) >> 2;
    uint2 q = ((uint2*)g_qs)[qq];
    uint2 kv = ((const uint2*)g_kvs)[((long)tb * 512 + c4 * 4) >> 2];
    q.x &= kv.x; q.y &= kv.y;
    ((uint2*)g_qs)[qq] = q;
}

// ---------------- HMMA GEMM with fused LIF epilogue ----------------
// Tile: M = 128 rows = 32 spatial x 4 timesteps (row = t*32 + nl), N = 128 channels,
// grid = (NN/32, Mch/128, BB). Warp m16 blocks at row mt*32 + wm*16 => mt == t,
// so LIF over t is a register-local loop over mt. 2 CTAs/SM, 256 thr.
// Epilogue per (n,c): val = acc*sA + sB (+Res); optional fp32 out; LIF(vth=1) -> spikes;
// optional vh float output for v-region channels (col >= 1024).
__global__ void __launch_bounds__(256, 2)
mma_lif(const __nv_bfloat16* __restrict__ A, int lda,
        const __nv_bfloat16* __restrict__ Whi, const __nv_bfloat16* __restrict__ Wlo,
        long wbase, int K,
        const float* __restrict__ Asc, const float* __restrict__ Bsc,
        const float* __restrict__ Res,           // fp32 [tb][n][MC] or null
        float* __restrict__ OutF,                // fp32 [tb][n][MC] or null
        __nv_bfloat16* __restrict__ OutS,        // spikes [tb][n][MC]
        int MC,                                  // output channel stride
        float* __restrict__ vh)                  // fp32 vh or null (qkv only)
{
    extern __shared__ char sm[];
    const uint32_t smb = smem_u32(sm);

    const int tid  = threadIdx.x;
    const int lane = tid & 31;
    const int wid  = tid >> 5;
    const int wm   = wid & 1;           // 2 m-groups (row offset wm*16 within each t)
    const int wn   = wid >> 1;          // 4 n-groups of 32 cols
    const int n0   = blockIdx.x * 32;   // spatial
    const int c0   = blockIdx.y * 128;  // channels
    const int b    = blockIdx.z;
    const int nch  = K >> 6;

    const __nv_bfloat16* Ab = A + ((long)b * 256 + n0) * lda;
    const __nv_bfloat16* Hb = Whi + wbase + (long)c0 * K;
    const __nv_bfloat16* Lb = Wlo + wbase + (long)c0 * K;

    const int arow = (lane & 7) + ((lane >> 3) & 1) * 8;
    const int ac8  = (lane >> 4) * 16;
    const int brow = (lane & 7) + (lane >> 4) * 8;
    const int bc8  = ((lane >> 3) & 1) * 16;

    float acc[4][4][4];
#pragma unroll
    for (int a_ = 0; a_ < 4; a_++)
#pragma unroll
        for (int b_ = 0; b_ < 4; b_++)
#pragma unroll
            for (int r_ = 0; r_ < 4; r_++) acc[a_][b_][r_] = 0.f;

    auto load_stage = [&](int s, int kc) {
        uint32_t base = smb + s * STAGE;
#pragma unroll
        for (int jj = 0; jj < 4; jj++) {
            int u = jj * 256 + tid;
            int r = u >> 3, c16 = u & 7;
            long grow = (long)(r >> 5) * 4096 + (r & 31);   // t*16*256 + nl rows
            cp16(base + r * RS + c16 * 16, Ab + grow * lda + kc * 64 + c16 * 8);
        }
#pragma unroll
        for (int jj = 0; jj < 4; jj++) {
            int u = jj * 256 + tid;
            int r = u >> 3, c16 = u & 7;
            cp16(base + STG_A + r * RS + c16 * 16, Hb + (long)r * K + kc * 64 + c16 * 8);
        }
#pragma unroll
        for (int jj = 0; jj < 4; jj++) {
            int u = jj * 256 + tid;
            int r = u >> 3, c16 = u & 7;
            cp16(base + 2 * STG_A + r * RS + c16 * 16, Lb + (long)r * K + kc * 64 + c16 * 8);
        }
    };

    load_stage(0, 0);
    CP_COMMIT();

    for (int ch = 0; ch < nch; ch++) {
        CP_WAIT0();
        __syncthreads();
        if (ch + 1 < nch) { load_stage((ch + 1) & 1, ch + 1); CP_COMMIT(); }

        const int s = ch & 1;
        const uint32_t ab = smb + s * STAGE;
        const uint32_t hb = ab + STG_A;
        const uint32_t lb = hb + STG_A;

#pragma unroll
        for (int kt = 0; kt < 4; kt++) {
            const int ko = kt * 32;
            uint32_t a[4][4];
#pragma unroll
            for (int mt = 0; mt < 4; mt++)
                ldm4(a[mt][0], a[mt][1], a[mt][2], a[mt][3],
                     ab + (mt * 32 + wm * 16 + arow) * RS + ko + ac8);

            uint32_t bh[8], bl[8];
#pragma unroll
            for (int p = 0; p < 2; p++)
                ldm4(bh[p*4+0], bh[p*4+1], bh[p*4+2], bh[p*4+3],
                     hb + (wn * 32 + p * 16 + brow) * RS + ko + bc8);
#pragma unroll
            for (int g = 0; g < 2; g++) {
                int bi = (g >> 1) * 4 + (g & 1) * 2;
#pragma unroll
                for (int mt = 0; mt < 4; mt++)
                    mma16816(acc[mt][g], a[mt], bh[bi], bh[bi + 1]);
            }
#pragma unroll
            for (int p = 0; p < 2; p++)
                ldm4(bl[p*4+0], bl[p*4+1], bl[p*4+2], bl[p*4+3],
                     lb + (wn * 32 + p * 16 + brow) * RS + ko + bc8);
#pragma unroll
            for (int g = 2; g < 4; g++) {
                int bi = (g >> 1) * 4 + (g & 1) * 2;
#pragma unroll
                for (int mt = 0; mt < 4; mt++)
                    mma16816(acc[mt][g], a[mt], bh[bi], bh[bi + 1]);
            }
#pragma unroll
            for (int g = 0; g < 4; g++) {
                int bi = (g >> 1) * 4 + (g & 1) * 2;
#pragma unroll
                for (int mt = 0; mt < 4; mt++)
                    mma16816(acc[mt][g], a[mt], bl[bi], bl[bi + 1]);
            }
        }
    }

    // ---------------- fused LIF epilogue ----------------
#pragma unroll
    for (int g = 0; g < 4; g++) {
        int col = c0 + wn * 32 + g * 8 + (lane & 3) * 2;
        float sA0 = Asc[col], sA1 = Asc[col + 1];
        float sB0 = Bsc[col], sB1 = Bsc[col + 1];
        bool dv = (vh != nullptr) && (col >= 1024);
        int h = 0, chv = 0;
        if (dv) { h = (col - 1024) >> 6; chv = (col - 1024) & 63; }
#pragma unroll
        for (int rv = 0; rv < 2; rv++) {
            int n = n0 + wm * 16 + (lane >> 2) + rv * 8;
            float v0 = 0.f, v1 = 0.f;
#pragma unroll
            for (int mt = 0; mt < 4; mt++) {
                long rowb = (long)(mt * BB + b) * 256 + n;
                float x0 = acc[mt][g][rv * 2 + 0] * sA0 + sB0;
                float x1 = acc[mt][g][rv * 2 + 1] * sA1 + sB1;
                if (Res) {
                    float2 rr = *(const float2*)(Res + rowb * MC + col);
                    x0 += rr.x; x1 += rr.y;
                }
                if (OutF) {
                    float2 w; w.x = x0; w.y = x1;
                    *(float2*)(OutF + rowb * MC + col) = w;
                }
                v0 = 0.5f * (v0 + x0);
                v1 = 0.5f * (v1 + x1);
                bool s0 = (v0 >= 1.0f), s1 = (v1 >= 1.0f);
                if (s0) v0 = 0.f;
                if (s1) v1 = 0.f;
                ushort2 sp;
                sp.x = s0 ? BF1 : 0;
                sp.y = s1 ? BF1 : 0;
                *(ushort2*)(OutS + rowb * MC + col) = sp;
                if (dv) {
                    float2 vo;
                    vo.x = s0 ? 1.f : 0.f;
                    vo.y = s1 ? 1.f : 0.f;
                    *(float2*)(vh + (((long)(mt * BB + b) * 8 + h) * 256 + n) * 64 + chv) = vo;
                }
            }
        }
    }
}

// ---------------- HMMA GEMM (fc2: channel-major out + residual) ----------------
__global__ void __launch_bounds__(256, 2)
mma_gemm(const __nv_bfloat16* __restrict__ A, long a_bs, int lda,
         const __nv_bfloat16* __restrict__ Whi, const __nv_bfloat16* __restrict__ Wlo,
         long wbase, int K,
         const float* __restrict__ Asc, const float* __restrict__ Bsc,
         const float* __restrict__ Res, long res_bs,
         float* __restrict__ Out, long out_bs, int Mout)
{
    extern __shared__ char sm[];
    const uint32_t smb = smem_u32(sm);

    const int tid  = threadIdx.x;
    const int lane = tid & 31;
    const int wid  = tid >> 5;
    const int wm   = wid & 1;
    const int wn   = wid >> 1;
    const int n0   = blockIdx.x * 128;
    const int c0   = blockIdx.y * 128;
    const int tb   = blockIdx.z;
    const int nch  = K >> 6;

    const __nv_bfloat16* Ab = A + (long)tb * a_bs + (long)n0 * lda;
    const __nv_bfloat16* Hb = Whi + wbase + (long)c0 * K;
    const __nv_bfloat16* Lb = Wlo + wbase + (long)c0 * K;

    const int arow = (lane & 7) + ((lane >> 3) & 1) * 8;
    const int ac8  = (lane >> 4) * 16;
    const int brow = (lane & 7) + (lane >> 4) * 8;
    const int bc8  = ((lane >> 3) & 1) * 16;

    float acc[4][4][4];
#pragma unroll
    for (int a_ = 0; a_ < 4; a_++)
#pragma unroll
        for (int b_ = 0; b_ < 4; b_++)
#pragma unroll
            for (int r_ = 0; r_ < 4; r_++) acc[a_][b_][r_] = 0.f;

    auto load_stage = [&](int s, int kc) {
        uint32_t base = smb + s * STAGE;
#pragma unroll
        for (int jj = 0; jj < 4; jj++) {
            int u = jj * 256 + tid;
            int r = u >> 3, c16 = u & 7;
            cp16(base + r * RS + c16 * 16, Ab + (long)r * lda + kc * 64 + c16 * 8);
        }
#pragma unroll
        for (int jj = 0; jj < 4; jj++) {
            int u = jj * 256 + tid;
            int r = u >> 3, c16 = u & 7;
            cp16(base + STG_A + r * RS + c16 * 16, Hb + (long)r * K + kc * 64 + c16 * 8);
        }
#pragma unroll
        for (int jj = 0; jj < 4; jj++) {
            int u = jj * 256 + tid;
            int r = u >> 3, c16 = u & 7;
            cp16(base + 2 * STG_A + r * RS + c16 * 16, Lb + (long)r * K + kc * 64 + c16 * 8);
        }
    };

    load_stage(0, 0);
    CP_COMMIT();

    for (int ch = 0; ch < nch; ch++) {
        CP_WAIT0();
        __syncthreads();
        if (ch + 1 < nch) { load_stage((ch + 1) & 1, ch + 1); CP_COMMIT(); }

        const int s = ch & 1;
        const uint32_t ab = smb + s * STAGE;
        const uint32_t hb = ab + STG_A;
        const uint32_t lb = hb + STG_A;

#pragma unroll
        for (int kt = 0; kt < 4; kt++) {
            const int ko = kt * 32;
            uint32_t a[4][4];
#pragma unroll
            for (int mt = 0; mt < 4; mt++)
                ldm4(a[mt][0], a[mt][1], a[mt][2], a[mt][3],
                     ab + (wm * 64 + mt * 16 + arow) * RS + ko + ac8);

            uint32_t bh[8], bl[8];
#pragma unroll
            for (int p = 0; p < 2; p++)
                ldm4(bh[p*4+0], bh[p*4+1], bh[p*4+2], bh[p*4+3],
                     hb + (wn * 32 + p * 16 + brow) * RS + ko + bc8);
#pragma unroll
            for (int g = 0; g < 2; g++) {
                int bi = (g >> 1) * 4 + (g & 1) * 2;
#pragma unroll
                for (int mt = 0; mt < 4; mt++)
                    mma16816(acc[mt][g], a[mt], bh[bi], bh[bi + 1]);
            }
#pragma unroll
            for (int p = 0; p < 2; p++)
                ldm4(bl[p*4+0], bl[p*4+1], bl[p*4+2], bl[p*4+3],
                     lb + (wn * 32 + p * 16 + brow) * RS + ko + bc8);
#pragma unroll
            for (int g = 2; g < 4; g++) {
                int bi = (g >> 1) * 4 + (g & 1) * 2;
#pragma unroll
                for (int mt = 0; mt < 4; mt++)
                    mma16816(acc[mt][g], a[mt], bh[bi], bh[bi + 1]);
            }
#pragma unroll
            for (int g = 0; g < 4; g++) {
                int bi = (g >> 1) * 4 + (g & 1) * 2;
#pragma unroll
                for (int mt = 0; mt < 4; mt++)
                    mma16816(acc[mt][g], a[mt], bl[bi], bl[bi + 1]);
            }
        }
    }
    __syncthreads();

    // channel-major epilogue: stage through smem for coalesced stores
    float* sf = (float*)sm;
#pragma unroll
    for (int mt = 0; mt < 4; mt++) {
#pragma unroll
        for (int g = 0; g < 4; g++) {
            int cl = wn * 32 + g * 8 + (lane & 3) * 2;
            int rl = wm * 64 + mt * 16 + (lane >> 2);
            int col = c0 + cl, row = n0 + rl;
            float sA0 = Asc[col], sA1 = Asc[col + 1];
            float sB0 = Bsc[col], sB1 = Bsc[col + 1];
            float v00 = acc[mt][g][0] * sA0 + sB0;
            float v01 = acc[mt][g][1] * sA1 + sB1;
            float v10 = acc[mt][g][2] * sA0 + sB0;
            float v11 = acc[mt][g][3] * sA1 + sB1;
            const float* r0 = Res + (long)tb * res_bs + (long)row * Mout + col;
            float2 ra = *(const float2*)r0;
            float2 rb = *(const float2*)(r0 + 8 * Mout);
            v00 += ra.x; v01 += ra.y; v10 += rb.x; v11 += rb.y;
            sf[cl * 132 + rl]           = v00;
            sf[(cl + 1) * 132 + rl]     = v01;
            sf[cl * 132 + rl + 8]       = v10;
            sf[(cl + 1) * 132 + rl + 8] = v11;
        }
    }
    __syncthreads();
#pragma unroll
    for (int i = 0; i < 16; i++) {
        int c = wid * 16 + i;
        float* orow = Out + (long)tb * out_bs + (long)(c0 + c) * NN + n0;
#pragma unroll
        for (int j = 0; j < 4; j++)
            orow[lane + j * 32] = sf[c * 132 + lane + j * 32];
    }
}

// ---------------- launch ----------------
extern "C" void kernel_launch(void* const* d_in, const int* in_sizes, int n_in,
                              void* d_out, int out_size)
{
    const float* x      = (const float*)d_in[0];
    const float* q_w    = (const float*)d_in[1];
    const float* k_w    = (const float*)d_in[2];
    const float* v_w    = (const float*)d_in[3];
    const float* proj_w = (const float*)d_in[4];
    const float* proj_b = (const float*)d_in[5];
    const float* fc1_w  = (const float*)d_in[6];
    const float* fc1_b  = (const float*)d_in[7];
    const float* fc2_w  = (const float*)d_in[8];
    const float* fc2_b  = (const float*)d_in[9];
    const float* q_bn   = (const float*)d_in[10];
    const float* k_bn   = (const float*)d_in[11];
    const float* v_bn   = (const float*)d_in[12];
    const float* proj_bn= (const float*)d_in[13];
    const float* fc1_bn = (const float*)d_in[14];
    const float* fc2_bn = (const float*)d_in[15];
    float* out = (float*)d_out;

    cudaFuncSetAttribute(mma_lif,  cudaFuncAttributeMaxDynamicSharedMemorySize, SMEM_TOT);
    cudaFuncSetAttribute(mma_gemm, cudaFuncAttributeMaxDynamicSharedMemorySize, SMEM_TOT);

    float *p_xt, *p_xat, *p_A, *p_Bc;
    __nv_bfloat16 *p_sx, *p_qs, *p_h1s, *p_whi, *p_wlo;
    cudaGetSymbolAddress((void**)&p_xt,  g_xt);
    cudaGetSymbolAddress((void**)&p_sx,  g_sx);
    cudaGetSymbolAddress((void**)&p_qs,  g_qs);
    cudaGetSymbolAddress((void**)&p_xat, g_xat);
    cudaGetSymbolAddress((void**)&p_h1s, g_h1s);
    cudaGetSymbolAddress((void**)&p_whi, g_whi);
    cudaGetSymbolAddress((void**)&p_wlo, g_wlo);
    cudaGetSymbolAddress((void**)&p_A,   g_A);
    cudaGetSymbolAddress((void**)&p_Bc,  g_Bc);

    // merged prep: BN fold + weight split + kvcnt zero + transpose/LIF of x
    prep_kernel<<<14482, 256>>>(q_bn, k_bn, v_bn, proj_bn, fc1_bn, fc2_bn,
                                proj_b, fc1_b, fc2_b,
                                q_w, k_w, v_w, proj_w, fc1_w, fc2_w, x);

    // qkv GEMM + fused LIF + vh: grid (8, 12, 16)
    mma_lif<<<dim3(8, 12, 16), 256, SMEM_TOT>>>(p_sx, CC,
                                                p_whi, p_wlo, W_QKV, CC,
                                                p_A, p_Bc,
                                                nullptr, nullptr,
                                                p_qs, 1536,
                                                out + (long)TBCN);

    kvcount_kernel<<<1024, 256>>>();
    kvlif2_kernel<<<32, 256>>>();
    att_kernel<<<8192, 256>>>();

    // proj GEMM + BN + identity(x) + fused MLP LIF: grid (8, 4, 16)
    mma_lif<<<dim3(8, 4, 16), 256, SMEM_TOT>>>(p_qs, 1536,
                                               p_whi, p_wlo, W_PROJ, CC,
                                               p_A + 1536, p_Bc + 1536,
                                               p_xt, p_xat,
                                               p_sx, CC,
                                               nullptr);

    // fc1 GEMM + fused LIF: grid (8, 16, 16)
    mma_lif<<<dim3(8, 16, 16), 256, SMEM_TOT>>>(p_sx, CC,
                                                p_whi, p_wlo, W_FC1, CC,
                                                p_A + 2048, p_Bc + 2048,
                                                nullptr, nullptr,
                                                p_h1s, HID,
                                                nullptr);

    // fc2 GEMM + BN + idm(x_attn) -> d_out (channel-major)
    mma_gemm<<<dim3(2, 4, 64), 256, SMEM_TOT>>>(p_h1s, (long)NN*HID, HID,
                                                p_whi, p_wlo, W_FC2, HID,
                                                p_A + 4096, p_Bc + 4096, p_xat, (long)NN*CC,
                                                out, (long)CC*NN, CC);
}